// round 1
// baseline (speedup 1.0000x reference)
#include <cuda_runtime.h>
#include <math.h>

#define LTOK 2048
#define DMODEL 256
#define NHEADS 8
#define HDIM 32
#define SCALE 0.17677669529663687f  /* 32^-0.5 */
#define LN_EPS 1e-5f

// ---------------- scratch (device globals; no allocation allowed) ----------------
__device__ float g_Q[LTOK * DMODEL];
__device__ float g_K[LTOK * DMODEL];
__device__ float g_V[LTOK * DMODEL];
__device__ float g_bias[LTOK * LTOK];   // beta * clip(bias), head-independent
__device__ float g_att[LTOK * DMODEL];  // attention output pre-projection
__device__ float g_proj[LTOK * DMODEL]; // x + attn @ Wo^T + bo (residual fused)

// ---------------------------------------------------------------------------------
// GEMM: C[m][n] = sum_k A[m][k] * W[n][k] + bias[n] (+ resid[m][n] if non-null)
// BM=BN=64, BK=16, 256 threads, 4x4 per thread.
// ---------------------------------------------------------------------------------
__global__ void __launch_bounds__(256) gemm_wt_bias(
    const float* __restrict__ A, const float* __restrict__ W,
    const float* __restrict__ bias, const float* __restrict__ resid,
    float* __restrict__ C, int M, int N, int K)
{
    __shared__ float As[16][68];
    __shared__ float Bs[16][68];
    const int tid = threadIdx.x;
    const int tx = tid & 15, ty = tid >> 4;
    const int m0 = blockIdx.y * 64, n0 = blockIdx.x * 64;

    const int lm = tid >> 2;          // 0..63
    const int lk = (tid & 3) << 2;    // 0,4,8,12
    const float* Ab = A + (m0 + lm) * K + lk;
    const float* Wb = W + (n0 + lm) * K + lk;

    float acc[4][4] = {};

    for (int k0 = 0; k0 < K; k0 += 16) {
        float4 av = *(const float4*)(Ab + k0);
        float4 wv = *(const float4*)(Wb + k0);
        As[lk + 0][lm] = av.x; As[lk + 1][lm] = av.y;
        As[lk + 2][lm] = av.z; As[lk + 3][lm] = av.w;
        Bs[lk + 0][lm] = wv.x; Bs[lk + 1][lm] = wv.y;
        Bs[lk + 2][lm] = wv.z; Bs[lk + 3][lm] = wv.w;
        __syncthreads();
        #pragma unroll
        for (int kk = 0; kk < 16; kk++) {
            float a[4], b[4];
            #pragma unroll
            for (int i = 0; i < 4; i++) a[i] = As[kk][ty * 4 + i];
            #pragma unroll
            for (int j = 0; j < 4; j++) b[j] = Bs[kk][tx * 4 + j];
            #pragma unroll
            for (int i = 0; i < 4; i++)
                #pragma unroll
                for (int j = 0; j < 4; j++)
                    acc[i][j] = fmaf(a[i], b[j], acc[i][j]);
        }
        __syncthreads();
    }

    #pragma unroll
    for (int i = 0; i < 4; i++) {
        const int m = m0 + ty * 4 + i;
        #pragma unroll
        for (int j = 0; j < 4; j++) {
            const int n = n0 + tx * 4 + j;
            float v = acc[i][j] + bias[n];
            if (resid) v += resid[m * N + n];
            C[m * N + n] = v;
        }
    }
}

// ---------------------------------------------------------------------------------
// Geometric bias: one block per query row; each thread does 8 keys.
// bias(q,k) = beta * clip( sum_j relu(dist*w1[j]+b1[j]) * w2[j] + b2, -10, 0 )
// ---------------------------------------------------------------------------------
__global__ void __launch_bounds__(256) geo_bias_kernel(
    const float* __restrict__ pts,
    const float* __restrict__ kw1, const float* __restrict__ kb1,
    const float* __restrict__ kw2, const float* __restrict__ kb2,
    const float* __restrict__ beta)
{
    __shared__ float sp[LTOK * 3];
    const int tid = threadIdx.x;
    for (int i = tid; i < LTOK * 3; i += 256) sp[i] = pts[i];
    __syncthreads();

    const int q = blockIdx.x;
    const float qx = sp[q * 3 + 0], qy = sp[q * 3 + 1], qz = sp[q * 3 + 2];

    float w1[32], b1[32], w2[32];
    #pragma unroll
    for (int j = 0; j < 32; j++) { w1[j] = kw1[j]; b1[j] = kb1[j]; w2[j] = kw2[j]; }
    const float b2 = kb2[0];
    const float bet = beta[0];

    for (int k = tid; k < LTOK; k += 256) {
        const float dx = qx - sp[k * 3 + 0];
        const float dy = qy - sp[k * 3 + 1];
        const float dz = qz - sp[k * 3 + 2];
        const float sq = dx * dx + dy * dy + dz * dz;
        const float dist = sqrtf(sq);
        float acc = b2;
        #pragma unroll
        for (int j = 0; j < 32; j++) {
            const float h = fmaxf(fmaf(dist, w1[j], b1[j]), 0.0f);
            acc = fmaf(h, w2[j], acc);
        }
        g_bias[q * LTOK + k] = bet * fminf(fmaxf(acc, -10.0f), 0.0f);
    }
}

// ---------------------------------------------------------------------------------
// Flash attention: one thread per query row (Q, acc in registers), one head per
// block, 128 query rows per block. K/V tiles (64 keys) staged in SMEM and read
// with uniform (broadcast) addresses. Bias row streamed from L2 with a
// one-chunk-ahead float4 prefetch. Online softmax in chunks of 8 keys.
// ---------------------------------------------------------------------------------
__global__ void __launch_bounds__(128) attn_kernel()
{
    __shared__ float4 Ks[64][8];
    __shared__ float4 Vs[64][8];

    const int tid = threadIdx.x;
    const int head = blockIdx.x >> 4;
    const int q = (blockIdx.x & 15) * 128 + tid;

    // Q row, pre-scaled
    float4 qv[8];
    const float4* qp = (const float4*)(g_Q + (size_t)q * DMODEL + head * HDIM);
    #pragma unroll
    for (int i = 0; i < 8; i++) {
        float4 t = qp[i];
        t.x *= SCALE; t.y *= SCALE; t.z *= SCALE; t.w *= SCALE;
        qv[i] = t;
    }

    float m = -INFINITY, l = 0.0f;
    float4 acc[8];
    #pragma unroll
    for (int i = 0; i < 8; i++) acc[i] = make_float4(0.f, 0.f, 0.f, 0.f);

    const float4* brow = (const float4*)(g_bias + (size_t)q * LTOK); // 512 float4
    float4 bA = brow[0], bB = brow[1];

    #pragma unroll 1
    for (int t0 = 0; t0 < LTOK; t0 += 64) {
        // cooperative K/V tile load (coalesced: each row is 128B contiguous)
        #pragma unroll
        for (int i = tid; i < 512; i += 128) {
            const int r = i >> 3, d4 = i & 7;
            Ks[r][d4] = ((const float4*)(g_K + (size_t)(t0 + r) * DMODEL + head * HDIM))[d4];
            Vs[r][d4] = ((const float4*)(g_V + (size_t)(t0 + r) * DMODEL + head * HDIM))[d4];
        }
        __syncthreads();

        #pragma unroll 1
        for (int c = 0; c < 8; ++c) {
            // prefetch next chunk's bias (global, L2-resident)
            const int cg = ((t0 >> 3) + c) + 1;
            float4 nA = make_float4(0.f, 0.f, 0.f, 0.f), nB = nA;
            if (cg < 256) { nA = brow[cg * 2]; nB = brow[cg * 2 + 1]; }

            float s[8] = { bA.x, bA.y, bA.z, bA.w, bB.x, bB.y, bB.z, bB.w };

            // scores: 8 independent FMA chains, broadcast LDS.128 of K
            #pragma unroll
            for (int d4 = 0; d4 < 8; d4++) {
                const float4 qq = qv[d4];
                #pragma unroll
                for (int j = 0; j < 8; j++) {
                    const float4 kk = Ks[c * 8 + j][d4];
                    s[j] = fmaf(qq.w, kk.w,
                           fmaf(qq.z, kk.z,
                           fmaf(qq.y, kk.y,
                           fmaf(qq.x, kk.x, s[j]))));
                }
            }

            // online softmax (chunk-granular rescale)
            float cm = s[0];
            #pragma unroll
            for (int j = 1; j < 8; j++) cm = fmaxf(cm, s[j]);
            const float mnew = fmaxf(m, cm);
            const float corr = __expf(m - mnew);   // exp(-inf)=0 on first chunk
            l *= corr;
            float p[8];
            #pragma unroll
            for (int j = 0; j < 8; j++) { p[j] = __expf(s[j] - mnew); l += p[j]; }

            #pragma unroll
            for (int d4 = 0; d4 < 8; d4++) {
                float4 a = acc[d4];
                a.x *= corr; a.y *= corr; a.z *= corr; a.w *= corr;
                #pragma unroll
                for (int j = 0; j < 8; j++) {
                    const float4 vv = Vs[c * 8 + j][d4];
                    a.x = fmaf(p[j], vv.x, a.x);
                    a.y = fmaf(p[j], vv.y, a.y);
                    a.z = fmaf(p[j], vv.z, a.z);
                    a.w = fmaf(p[j], vv.w, a.w);
                }
                acc[d4] = a;
            }
            m = mnew;
            bA = nA; bB = nB;
        }
        __syncthreads();
    }

    const float inv = 1.0f / l;
    float4* op = (float4*)(g_att + (size_t)q * DMODEL + head * HDIM);
    #pragma unroll
    for (int d4 = 0; d4 < 8; d4++) {
        float4 a = acc[d4];
        a.x *= inv; a.y *= inv; a.z *= inv; a.w *= inv;
        op[d4] = a;
    }
}

// ---------------------------------------------------------------------------------
// LayerNorm over last dim (256). One block per row. y already includes residual.
// ---------------------------------------------------------------------------------
__global__ void __launch_bounds__(256) ln_kernel(
    const float* __restrict__ y, const float* __restrict__ g,
    const float* __restrict__ b, float* __restrict__ out)
{
    __shared__ float red[16];
    const int row = blockIdx.x, t = threadIdx.x;
    const float v = y[row * DMODEL + t];

    float s = v;
    #pragma unroll
    for (int o = 16; o; o >>= 1) s += __shfl_xor_sync(0xffffffffu, s, o);
    if ((t & 31) == 0) red[t >> 5] = s;
    __syncthreads();
    float tot = 0.f;
    #pragma unroll
    for (int w = 0; w < 8; w++) tot += red[w];
    const float mu = tot * (1.0f / 256.0f);

    const float d = v - mu;
    float sq = d * d;
    #pragma unroll
    for (int o = 16; o; o >>= 1) sq += __shfl_xor_sync(0xffffffffu, sq, o);
    if ((t & 31) == 0) red[8 + (t >> 5)] = sq;
    __syncthreads();
    float tot2 = 0.f;
    #pragma unroll
    for (int w = 0; w < 8; w++) tot2 += red[8 + w];
    const float var = tot2 * (1.0f / 256.0f);

    out[row * DMODEL + t] = d * rsqrtf(var + LN_EPS) * g[t] + b[t];
}

// ---------------------------------------------------------------------------------
extern "C" void kernel_launch(void* const* d_in, const int* in_sizes, int n_in,
                              void* d_out, int out_size)
{
    const float* x    = (const float*)d_in[0];
    const float* pts  = (const float*)d_in[1];
    const float* Wq   = (const float*)d_in[2];
    const float* bq   = (const float*)d_in[3];
    const float* Wk   = (const float*)d_in[4];
    const float* bk   = (const float*)d_in[5];
    const float* Wv   = (const float*)d_in[6];
    const float* bv   = (const float*)d_in[7];
    const float* Wo   = (const float*)d_in[8];
    const float* bo   = (const float*)d_in[9];
    const float* beta = (const float*)d_in[10];
    const float* kw1  = (const float*)d_in[11];
    const float* kb1  = (const float*)d_in[12];
    const float* kw2  = (const float*)d_in[13];
    const float* kb2  = (const float*)d_in[14];
    const float* lng  = (const float*)d_in[15];
    const float* lnb  = (const float*)d_in[16];
    float* out = (float*)d_out;

    float *Qb, *Kb, *Vb, *Ab, *Pb;
    cudaGetSymbolAddress((void**)&Qb, g_Q);
    cudaGetSymbolAddress((void**)&Kb, g_K);
    cudaGetSymbolAddress((void**)&Vb, g_V);
    cudaGetSymbolAddress((void**)&Ab, g_att);
    cudaGetSymbolAddress((void**)&Pb, g_proj);

    const dim3 ggrid(DMODEL / 64, LTOK / 64);  // (4, 32)

    // QKV projections
    gemm_wt_bias<<<ggrid, 256>>>(x, Wq, bq, nullptr, Qb, LTOK, DMODEL, DMODEL);
    gemm_wt_bias<<<ggrid, 256>>>(x, Wk, bk, nullptr, Kb, LTOK, DMODEL, DMODEL);
    gemm_wt_bias<<<ggrid, 256>>>(x, Wv, bv, nullptr, Vb, LTOK, DMODEL, DMODEL);

    // geometric bias (head-independent, computed once)
    geo_bias_kernel<<<LTOK, 256>>>(pts, kw1, kb1, kw2, kb2, beta);

    // flash attention: 8 heads x 16 row-tiles
    attn_kernel<<<NHEADS * 16, 128>>>();

    // output projection + residual (fused)
    gemm_wt_bias<<<ggrid, 256>>>(Ab, Wo, bo, x, Pb, LTOK, DMODEL, DMODEL);

    // LayerNorm -> final output
    ln_kernel<<<LTOK, 256>>>(Pb, lng, lnb, out);
}

// round 2
// speedup vs baseline: 1.2234x; 1.2234x over previous
#include <cuda_runtime.h>
#include <math.h>

#define LTOK 2048
#define DMODEL 256
#define NHEADS 8
#define HDIM 32
#define SCALE 0.17677669529663687f  /* 32^-0.5 */
#define LN_EPS 1e-5f
#define SPLIT 8
#define SPLIT_LOG 3
#define KEYS_PER_SPLIT (LTOK / SPLIT)   /* 256 */
#define NROWS (NHEADS * LTOK)           /* 16384 */

// ---------------- scratch (device globals; no allocation allowed) ----------------
__device__ float g_Q[LTOK * DMODEL];
__device__ float g_K[LTOK * DMODEL];
__device__ float g_V[LTOK * DMODEL];
__device__ float g_bias[LTOK * LTOK];     // beta * clip(bias), head-independent
__device__ float g_att[LTOK * DMODEL];    // attention output pre-projection
__device__ float g_proj[LTOK * DMODEL];   // x + attn @ Wo^T + bo
__device__ float g_pacc[SPLIT * NROWS * HDIM]; // split-K partial (unnormalized)
__device__ float g_pm[SPLIT * NROWS];
__device__ float g_pl[SPLIT * NROWS];
// piecewise-linear tables for the geometric-bias MLP
__device__ float g_T[32];   // sorted thresholds (padded +INF)
__device__ float g_S[33];   // prefix slopes
__device__ float g_C[33];   // prefix intercepts

// ---------------------------------------------------------------------------------
// GEMM: C[m][n] = sum_k A[m][k] * W[n][k] + bias[n] (+ resid). 64x64x16, 4x4/thread.
// ---------------------------------------------------------------------------------
__device__ __forceinline__ void gemm_body(
    const float* __restrict__ A, const float* __restrict__ W,
    const float* __restrict__ bias, const float* __restrict__ resid,
    float* __restrict__ C, int K, int N,
    float As[16][68], float Bs[16][68])
{
    const int tid = threadIdx.x;
    const int tx = tid & 15, ty = tid >> 4;
    const int m0 = blockIdx.y * 64, n0 = blockIdx.x * 64;

    const int lm = tid >> 2;
    const int lk = (tid & 3) << 2;
    const float* Ab = A + (m0 + lm) * K + lk;
    const float* Wb = W + (n0 + lm) * K + lk;

    float acc[4][4] = {};

    for (int k0 = 0; k0 < K; k0 += 16) {
        float4 av = *(const float4*)(Ab + k0);
        float4 wv = *(const float4*)(Wb + k0);
        As[lk + 0][lm] = av.x; As[lk + 1][lm] = av.y;
        As[lk + 2][lm] = av.z; As[lk + 3][lm] = av.w;
        Bs[lk + 0][lm] = wv.x; Bs[lk + 1][lm] = wv.y;
        Bs[lk + 2][lm] = wv.z; Bs[lk + 3][lm] = wv.w;
        __syncthreads();
        #pragma unroll
        for (int kk = 0; kk < 16; kk++) {
            float a[4], b[4];
            #pragma unroll
            for (int i = 0; i < 4; i++) a[i] = As[kk][ty * 4 + i];
            #pragma unroll
            for (int j = 0; j < 4; j++) b[j] = Bs[kk][tx * 4 + j];
            #pragma unroll
            for (int i = 0; i < 4; i++)
                #pragma unroll
                for (int j = 0; j < 4; j++)
                    acc[i][j] = fmaf(a[i], b[j], acc[i][j]);
        }
        __syncthreads();
    }

    #pragma unroll
    for (int i = 0; i < 4; i++) {
        const int m = m0 + ty * 4 + i;
        #pragma unroll
        for (int j = 0; j < 4; j++) {
            const int n = n0 + tx * 4 + j;
            float v = acc[i][j] + bias[n];
            if (resid) v += resid[m * N + n];
            C[m * N + n] = v;
        }
    }
}

__global__ void __launch_bounds__(256) gemm_qkv(
    const float* __restrict__ x,
    const float* __restrict__ Wq, const float* __restrict__ bq,
    const float* __restrict__ Wk, const float* __restrict__ bk,
    const float* __restrict__ Wv, const float* __restrict__ bv,
    float* __restrict__ Qo, float* __restrict__ Ko, float* __restrict__ Vo)
{
    __shared__ float As[16][68];
    __shared__ float Bs[16][68];
    const float* W; const float* b; float* C;
    if (blockIdx.z == 0)      { W = Wq; b = bq; C = Qo; }
    else if (blockIdx.z == 1) { W = Wk; b = bk; C = Ko; }
    else                      { W = Wv; b = bv; C = Vo; }
    gemm_body(x, W, b, nullptr, C, DMODEL, DMODEL, As, Bs);
}

__global__ void __launch_bounds__(256) gemm_o(
    const float* __restrict__ A, const float* __restrict__ W,
    const float* __restrict__ b, const float* __restrict__ resid,
    float* __restrict__ C)
{
    __shared__ float As[16][68];
    __shared__ float Bs[16][68];
    gemm_body(A, W, b, resid, C, DMODEL, DMODEL, As, Bs);
}

// ---------------------------------------------------------------------------------
// Setup: the bias MLP  clip(sum_j relu(d*w1+b1)*w2 + b2)  is piecewise-linear in d.
// Build sorted activation thresholds + prefix slope/intercept tables. 1 thread.
// ---------------------------------------------------------------------------------
__global__ void setup_geo_tables(
    const float* __restrict__ kw1, const float* __restrict__ kb1,
    const float* __restrict__ kw2, const float* __restrict__ kb2)
{
    float t[32], ds[32], dc[32];
    int n = 0;
    float S0 = 0.0f, C0 = kb2[0];
    for (int j = 0; j < 32; j++) {
        const float w1 = kw1[j], b1 = kb1[j], w2 = kw2[j];
        if (b1 > 0.0f) { S0 += w1 * w2; C0 += b1 * w2; }   // active at d=0
        if (w1 > 0.0f && !(b1 > 0.0f)) {                   // activates at tj >= 0
            t[n] = -b1 / w1; ds[n] = w1 * w2; dc[n] = b1 * w2; n++;
        } else if (w1 < 0.0f && b1 > 0.0f) {               // deactivates at tj > 0
            t[n] = -b1 / w1; ds[n] = -w1 * w2; dc[n] = -b1 * w2; n++;
        }
    }
    // insertion sort by threshold
    for (int i = 1; i < n; i++) {
        float tv = t[i], sv = ds[i], cv = dc[i];
        int j = i - 1;
        while (j >= 0 && t[j] > tv) { t[j+1]=t[j]; ds[j+1]=ds[j]; dc[j+1]=dc[j]; j--; }
        t[j+1] = tv; ds[j+1] = sv; dc[j+1] = cv;
    }
    g_S[0] = S0; g_C[0] = C0;
    for (int i = 0; i < 32; i++) {
        if (i < n) {
            g_T[i] = t[i];
            g_S[i+1] = g_S[i] + ds[i];
            g_C[i+1] = g_C[i] + dc[i];
        } else {
            g_T[i] = INFINITY;
            g_S[i+1] = g_S[i];
            g_C[i+1] = g_C[i];
        }
    }
}

// ---------------------------------------------------------------------------------
// Geometric bias via table: d = |p_q - p_k|; idx = #{T < d}; bias = S[idx]*d + C[idx]
// 512 blocks x 4 query rows, 256 threads.
// ---------------------------------------------------------------------------------
__global__ void __launch_bounds__(256) geo_bias_kernel(
    const float* __restrict__ pts, const float* __restrict__ beta)
{
    __shared__ float sp[LTOK * 3];
    __shared__ float sT[32], sS[33], sC[33];
    const int tid = threadIdx.x;
    for (int i = tid; i < LTOK * 3; i += 256) sp[i] = pts[i];
    if (tid < 32) sT[tid] = g_T[tid];
    if (tid < 33) { sS[tid] = g_S[tid]; sC[tid] = g_C[tid]; }
    __syncthreads();

    const float bet = beta[0];
    const int qbase = blockIdx.x * 4;

    #pragma unroll
    for (int qi = 0; qi < 4; qi++) {
        const int q = qbase + qi;
        const float qx = sp[q*3+0], qy = sp[q*3+1], qz = sp[q*3+2];
        for (int k = tid; k < LTOK; k += 256) {
            const float dx = qx - sp[k*3+0];
            const float dy = qy - sp[k*3+1];
            const float dz = qz - sp[k*3+2];
            const float d = sqrtf(dx*dx + dy*dy + dz*dz);
            int i = 0;
            #pragma unroll
            for (int s = 16; s; s >>= 1) if (sT[i + s - 1] < d) i += s;
            const float b = fmaf(sS[i], d, sC[i]);
            g_bias[q * LTOK + k] = bet * fminf(fmaxf(b, -10.0f), 0.0f);
        }
    }
}

// ---------------------------------------------------------------------------------
// Split-K flash attention. Block = (head, qtile, split); 128 threads = 128 q rows;
// each block covers 256 keys. Writes unnormalized (acc, m, l) partials.
// ---------------------------------------------------------------------------------
__global__ void __launch_bounds__(128) attn_kernel()
{
    __shared__ float4 Ks[64][8];
    __shared__ float4 Vs[64][8];

    const int tid  = threadIdx.x;
    const int split = blockIdx.x & (SPLIT - 1);
    const int tile  = (blockIdx.x >> SPLIT_LOG) & 15;
    const int head  = blockIdx.x >> (SPLIT_LOG + 4);
    const int q = tile * 128 + tid;
    const int kbeg = split * KEYS_PER_SPLIT;

    float4 qv[8];
    const float4* qp = (const float4*)(g_Q + (size_t)q * DMODEL + head * HDIM);
    #pragma unroll
    for (int i = 0; i < 8; i++) {
        float4 t = qp[i];
        t.x *= SCALE; t.y *= SCALE; t.z *= SCALE; t.w *= SCALE;
        qv[i] = t;
    }

    float m = -INFINITY, l = 0.0f;
    float4 acc[8];
    #pragma unroll
    for (int i = 0; i < 8; i++) acc[i] = make_float4(0.f, 0.f, 0.f, 0.f);

    const float4* brow = (const float4*)(g_bias + (size_t)q * LTOK);
    float4 bA = brow[(kbeg >> 3) * 2], bB = brow[(kbeg >> 3) * 2 + 1];

    #pragma unroll 1
    for (int t0 = kbeg; t0 < kbeg + KEYS_PER_SPLIT; t0 += 64) {
        #pragma unroll
        for (int i = tid; i < 512; i += 128) {
            const int r = i >> 3, d4 = i & 7;
            Ks[r][d4] = ((const float4*)(g_K + (size_t)(t0 + r) * DMODEL + head * HDIM))[d4];
            Vs[r][d4] = ((const float4*)(g_V + (size_t)(t0 + r) * DMODEL + head * HDIM))[d4];
        }
        __syncthreads();

        #pragma unroll 1
        for (int c = 0; c < 8; ++c) {
            const int cg = (t0 >> 3) + c + 1;  // next chunk (global index)
            float4 nA = make_float4(0.f,0.f,0.f,0.f), nB = nA;
            if (cg < (kbeg + KEYS_PER_SPLIT) >> 3) { nA = brow[cg*2]; nB = brow[cg*2+1]; }

            float s[8] = { bA.x, bA.y, bA.z, bA.w, bB.x, bB.y, bB.z, bB.w };

            #pragma unroll
            for (int d4 = 0; d4 < 8; d4++) {
                const float4 qq = qv[d4];
                #pragma unroll
                for (int j = 0; j < 8; j++) {
                    const float4 kk = Ks[c * 8 + j][d4];
                    s[j] = fmaf(qq.w, kk.w,
                           fmaf(qq.z, kk.z,
                           fmaf(qq.y, kk.y,
                           fmaf(qq.x, kk.x, s[j]))));
                }
            }

            float cm = s[0];
            #pragma unroll
            for (int j = 1; j < 8; j++) cm = fmaxf(cm, s[j]);
            const float mnew = fmaxf(m, cm);
            const float corr = __expf(m - mnew);
            l *= corr;
            float p[8];
            #pragma unroll
            for (int j = 0; j < 8; j++) { p[j] = __expf(s[j] - mnew); l += p[j]; }

            #pragma unroll
            for (int d4 = 0; d4 < 8; d4++) {
                float4 a = acc[d4];
                a.x *= corr; a.y *= corr; a.z *= corr; a.w *= corr;
                #pragma unroll
                for (int j = 0; j < 8; j++) {
                    const float4 vv = Vs[c * 8 + j][d4];
                    a.x = fmaf(p[j], vv.x, a.x);
                    a.y = fmaf(p[j], vv.y, a.y);
                    a.z = fmaf(p[j], vv.z, a.z);
                    a.w = fmaf(p[j], vv.w, a.w);
                }
                acc[d4] = a;
            }
            m = mnew;
            bA = nA; bB = nB;
        }
        __syncthreads();
    }

    const int row = head * LTOK + q;
    float4* op = (float4*)(g_pacc + ((size_t)split * NROWS + row) * HDIM);
    #pragma unroll
    for (int d4 = 0; d4 < 8; d4++) op[d4] = acc[d4];
    g_pm[split * NROWS + row] = m;
    g_pl[split * NROWS + row] = l;
}

// ---------------------------------------------------------------------------------
// Merge split-K partials: o = sum_s e^{m_s-m*} acc_s / sum_s e^{m_s-m*} l_s
// One thread per (row, d4): 16384*8 threads.
// ---------------------------------------------------------------------------------
__global__ void __launch_bounds__(256) merge_kernel()
{
    const int idx = blockIdx.x * 256 + threadIdx.x;
    const int row = idx >> 3, d4 = idx & 7;

    float mv[SPLIT];
    float mstar = -INFINITY;
    #pragma unroll
    for (int s = 0; s < SPLIT; s++) {
        mv[s] = g_pm[s * NROWS + row];
        mstar = fmaxf(mstar, mv[s]);
    }
    float denom = 0.0f;
    float4 o = make_float4(0.f, 0.f, 0.f, 0.f);
    #pragma unroll
    for (int s = 0; s < SPLIT; s++) {
        const float w = __expf(mv[s] - mstar);
        denom = fmaf(w, g_pl[s * NROWS + row], denom);
        const float4 a = *(const float4*)(g_pacc + ((size_t)s * NROWS + row) * HDIM + d4 * 4);
        o.x = fmaf(w, a.x, o.x);
        o.y = fmaf(w, a.y, o.y);
        o.z = fmaf(w, a.z, o.z);
        o.w = fmaf(w, a.w, o.w);
    }
    const float inv = 1.0f / denom;
    o.x *= inv; o.y *= inv; o.z *= inv; o.w *= inv;

    const int head = row >> 11, q = row & (LTOK - 1);
    *(float4*)(g_att + (size_t)q * DMODEL + head * HDIM + d4 * 4) = o;
}

// ---------------------------------------------------------------------------------
// LayerNorm over last dim (256). One block per row.
// ---------------------------------------------------------------------------------
__global__ void __launch_bounds__(256) ln_kernel(
    const float* __restrict__ y, const float* __restrict__ g,
    const float* __restrict__ b, float* __restrict__ out)
{
    __shared__ float red[16];
    const int row = blockIdx.x, t = threadIdx.x;
    const float v = y[row * DMODEL + t];

    float s = v;
    #pragma unroll
    for (int o = 16; o; o >>= 1) s += __shfl_xor_sync(0xffffffffu, s, o);
    if ((t & 31) == 0) red[t >> 5] = s;
    __syncthreads();
    float tot = 0.f;
    #pragma unroll
    for (int w = 0; w < 8; w++) tot += red[w];
    const float mu = tot * (1.0f / 256.0f);

    const float d = v - mu;
    float sq = d * d;
    #pragma unroll
    for (int o = 16; o; o >>= 1) sq += __shfl_xor_sync(0xffffffffu, sq, o);
    if ((t & 31) == 0) red[8 + (t >> 5)] = sq;
    __syncthreads();
    float tot2 = 0.f;
    #pragma unroll
    for (int w = 0; w < 8; w++) tot2 += red[8 + w];
    const float var = tot2 * (1.0f / 256.0f);

    out[row * DMODEL + t] = d * rsqrtf(var + LN_EPS) * g[t] + b[t];
}

// ---------------------------------------------------------------------------------
extern "C" void kernel_launch(void* const* d_in, const int* in_sizes, int n_in,
                              void* d_out, int out_size)
{
    const float* x    = (const float*)d_in[0];
    const float* pts  = (const float*)d_in[1];
    const float* Wq   = (const float*)d_in[2];
    const float* bq   = (const float*)d_in[3];
    const float* Wk   = (const float*)d_in[4];
    const float* bk   = (const float*)d_in[5];
    const float* Wv   = (const float*)d_in[6];
    const float* bv   = (const float*)d_in[7];
    const float* Wo   = (const float*)d_in[8];
    const float* bo   = (const float*)d_in[9];
    const float* beta = (const float*)d_in[10];
    const float* kw1  = (const float*)d_in[11];
    const float* kb1  = (const float*)d_in[12];
    const float* kw2  = (const float*)d_in[13];
    const float* kb2  = (const float*)d_in[14];
    const float* lng  = (const float*)d_in[15];
    const float* lnb  = (const float*)d_in[16];
    float* out = (float*)d_out;

    float *Qb, *Kb, *Vb, *Ab, *Pb;
    cudaGetSymbolAddress((void**)&Qb, g_Q);
    cudaGetSymbolAddress((void**)&Kb, g_K);
    cudaGetSymbolAddress((void**)&Vb, g_V);
    cudaGetSymbolAddress((void**)&Ab, g_att);
    cudaGetSymbolAddress((void**)&Pb, g_proj);

    setup_geo_tables<<<1, 1>>>(kw1, kb1, kw2, kb2);

    // fused QKV projections: grid.z selects weight set
    gemm_qkv<<<dim3(DMODEL/64, LTOK/64, 3), 256>>>(x, Wq, bq, Wk, bk, Wv, bv, Qb, Kb, Vb);

    // geometric bias (head-independent)
    geo_bias_kernel<<<LTOK / 4, 256>>>(pts, beta);

    // split-K flash attention + merge
    attn_kernel<<<NHEADS * 16 * SPLIT, 128>>>();
    merge_kernel<<<NROWS * 8 / 256, 256>>>();

    // output projection + residual
    gemm_o<<<dim3(DMODEL/64, LTOK/64), 256>>>(Ab, Wo, bo, x, Pb);

    // LayerNorm
    ln_kernel<<<LTOK, 256>>>(Pb, lng, lnb, out);
}

// round 3
// speedup vs baseline: 1.3237x; 1.0820x over previous
#include <cuda_runtime.h>
#include <math.h>

#define LTOK 2048
#define DMODEL 256
#define NHEADS 8
#define HDIM 32
#define SCALE 0.17677669529663687f  /* 32^-0.5 */
#define LN_EPS 1e-5f
#define SPLIT 8
#define KEYS_PER_SPLIT (LTOK / SPLIT)   /* 256 */
#define NROWS (NHEADS * LTOK)           /* 16384 */

// ---------------- scratch (device globals; no allocation allowed) ----------------
__device__ float g_Q[LTOK * DMODEL];
__device__ float g_K[LTOK * DMODEL];
__device__ float g_V[LTOK * DMODEL];
__device__ float g_bias[LTOK * LTOK];     // beta * clip(bias), head-independent
__device__ float g_att[LTOK * DMODEL];    // attention output pre-projection
__device__ float g_proj[LTOK * DMODEL];   // x + attn @ Wo^T + bo
__device__ float g_pacc[SPLIT * NROWS * HDIM]; // split-K partial (unnormalized)
__device__ float g_pm[SPLIT * NROWS];
__device__ float g_pl[SPLIT * NROWS];
// piecewise-linear tables for the geometric-bias MLP
__device__ float g_T[32];   // sorted thresholds (padded +INF)
__device__ float g_S[33];   // prefix slopes
__device__ float g_C[33];   // prefix intercepts

// ---------------------------------------------------------------------------------
// GEMM: C[m][n] = sum_k A[m][k] * W[n][k] + bias[n] (+ resid). 64x64x16, 4x4/thread.
// ---------------------------------------------------------------------------------
__device__ __forceinline__ void gemm_body(
    const float* __restrict__ A, const float* __restrict__ W,
    const float* __restrict__ bias, const float* __restrict__ resid,
    float* __restrict__ C, int K, int N,
    float As[16][68], float Bs[16][68])
{
    const int tid = threadIdx.x;
    const int tx = tid & 15, ty = tid >> 4;
    const int m0 = blockIdx.y * 64, n0 = blockIdx.x * 64;

    const int lm = tid >> 2;
    const int lk = (tid & 3) << 2;
    const float* Ab = A + (m0 + lm) * K + lk;
    const float* Wb = W + (n0 + lm) * K + lk;

    float acc[4][4] = {};

    for (int k0 = 0; k0 < K; k0 += 16) {
        float4 av = *(const float4*)(Ab + k0);
        float4 wv = *(const float4*)(Wb + k0);
        As[lk + 0][lm] = av.x; As[lk + 1][lm] = av.y;
        As[lk + 2][lm] = av.z; As[lk + 3][lm] = av.w;
        Bs[lk + 0][lm] = wv.x; Bs[lk + 1][lm] = wv.y;
        Bs[lk + 2][lm] = wv.z; Bs[lk + 3][lm] = wv.w;
        __syncthreads();
        #pragma unroll
        for (int kk = 0; kk < 16; kk++) {
            float a[4], b[4];
            #pragma unroll
            for (int i = 0; i < 4; i++) a[i] = As[kk][ty * 4 + i];
            #pragma unroll
            for (int j = 0; j < 4; j++) b[j] = Bs[kk][tx * 4 + j];
            #pragma unroll
            for (int i = 0; i < 4; i++)
                #pragma unroll
                for (int j = 0; j < 4; j++)
                    acc[i][j] = fmaf(a[i], b[j], acc[i][j]);
        }
        __syncthreads();
    }

    #pragma unroll
    for (int i = 0; i < 4; i++) {
        const int m = m0 + ty * 4 + i;
        #pragma unroll
        for (int j = 0; j < 4; j++) {
            const int n = n0 + tx * 4 + j;
            float v = acc[i][j] + bias[n];
            if (resid) v += resid[m * N + n];
            C[m * N + n] = v;
        }
    }
}

__global__ void __launch_bounds__(256) gemm_qkv(
    const float* __restrict__ x,
    const float* __restrict__ Wq, const float* __restrict__ bq,
    const float* __restrict__ Wk, const float* __restrict__ bk,
    const float* __restrict__ Wv, const float* __restrict__ bv,
    float* __restrict__ Qo, float* __restrict__ Ko, float* __restrict__ Vo)
{
    __shared__ float As[16][68];
    __shared__ float Bs[16][68];
    const float* W; const float* b; float* C;
    if (blockIdx.z == 0)      { W = Wq; b = bq; C = Qo; }
    else if (blockIdx.z == 1) { W = Wk; b = bk; C = Ko; }
    else                      { W = Wv; b = bv; C = Vo; }
    gemm_body(x, W, b, nullptr, C, DMODEL, DMODEL, As, Bs);
}

__global__ void __launch_bounds__(256) gemm_o(
    const float* __restrict__ A, const float* __restrict__ W,
    const float* __restrict__ b, const float* __restrict__ resid,
    float* __restrict__ C)
{
    __shared__ float As[16][68];
    __shared__ float Bs[16][68];
    gemm_body(A, W, b, resid, C, DMODEL, DMODEL, As, Bs);
}

// ---------------------------------------------------------------------------------
// Setup: bias MLP is piecewise-linear in d; build threshold/prefix tables. 1 thread.
// ---------------------------------------------------------------------------------
__global__ void setup_geo_tables(
    const float* __restrict__ kw1, const float* __restrict__ kb1,
    const float* __restrict__ kw2, const float* __restrict__ kb2)
{
    float t[32], ds[32], dc[32];
    int n = 0;
    float S0 = 0.0f, C0 = kb2[0];
    for (int j = 0; j < 32; j++) {
        const float w1 = kw1[j], b1 = kb1[j], w2 = kw2[j];
        if (b1 > 0.0f) { S0 += w1 * w2; C0 += b1 * w2; }
        if (w1 > 0.0f && !(b1 > 0.0f)) {
            t[n] = -b1 / w1; ds[n] = w1 * w2; dc[n] = b1 * w2; n++;
        } else if (w1 < 0.0f && b1 > 0.0f) {
            t[n] = -b1 / w1; ds[n] = -w1 * w2; dc[n] = -b1 * w2; n++;
        }
    }
    for (int i = 1; i < n; i++) {
        float tv = t[i], sv = ds[i], cv = dc[i];
        int j = i - 1;
        while (j >= 0 && t[j] > tv) { t[j+1]=t[j]; ds[j+1]=ds[j]; dc[j+1]=dc[j]; j--; }
        t[j+1] = tv; ds[j+1] = sv; dc[j+1] = cv;
    }
    g_S[0] = S0; g_C[0] = C0;
    for (int i = 0; i < 32; i++) {
        if (i < n) {
            g_T[i] = t[i];
            g_S[i+1] = g_S[i] + ds[i];
            g_C[i+1] = g_C[i] + dc[i];
        } else {
            g_T[i] = INFINITY;
            g_S[i+1] = g_S[i];
            g_C[i+1] = g_C[i];
        }
    }
}

// ---------------------------------------------------------------------------------
// Geometric bias via table lookup. 512 blocks x 4 query rows, 256 threads.
// ---------------------------------------------------------------------------------
__global__ void __launch_bounds__(256) geo_bias_kernel(
    const float* __restrict__ pts, const float* __restrict__ beta)
{
    __shared__ float sp[LTOK * 3];
    __shared__ float sT[32], sS[33], sC[33];
    const int tid = threadIdx.x;
    for (int i = tid; i < LTOK * 3; i += 256) sp[i] = pts[i];
    if (tid < 32) sT[tid] = g_T[tid];
    if (tid < 33) { sS[tid] = g_S[tid]; sC[tid] = g_C[tid]; }
    __syncthreads();

    const float bet = beta[0];
    const int qbase = blockIdx.x * 4;

    #pragma unroll
    for (int qi = 0; qi < 4; qi++) {
        const int q = qbase + qi;
        const float qx = sp[q*3+0], qy = sp[q*3+1], qz = sp[q*3+2];
        for (int k = tid; k < LTOK; k += 256) {
            const float dx = qx - sp[k*3+0];
            const float dy = qy - sp[k*3+1];
            const float dz = qz - sp[k*3+2];
            const float d = sqrtf(dx*dx + dy*dy + dz*dz);
            int i = 0;
            #pragma unroll
            for (int s = 16; s; s >>= 1) if (sT[i + s - 1] < d) i += s;
            const float b = fmaf(sS[i], d, sC[i]);
            g_bias[q * LTOK + k] = bet * fminf(fmaxf(b, -10.0f), 0.0f);
        }
    }
}

// ---------------------------------------------------------------------------------
// Split-K flash attention, 2 QUERY ROWS PER THREAD (halves LDS instrs per q).
// Block = (head, qtile(256 rows), split); 128 threads; 256 keys per block.
// ---------------------------------------------------------------------------------
__global__ void __launch_bounds__(128) attn_kernel()
{
    __shared__ float4 Ks[64][8];
    __shared__ float4 Vs[64][8];

    const int tid   = threadIdx.x;
    const int split = blockIdx.x & (SPLIT - 1);
    const int tile  = (blockIdx.x >> 3) & 7;
    const int head  = blockIdx.x >> 6;
    const int q0 = tile * 256 + tid;
    const int q1 = q0 + 128;
    const int kbeg = split * KEYS_PER_SPLIT;

    float4 qv0[8], qv1[8];
    {
        const float4* qp0 = (const float4*)(g_Q + (size_t)q0 * DMODEL + head * HDIM);
        const float4* qp1 = (const float4*)(g_Q + (size_t)q1 * DMODEL + head * HDIM);
        #pragma unroll
        for (int i = 0; i < 8; i++) {
            float4 t = qp0[i];
            t.x *= SCALE; t.y *= SCALE; t.z *= SCALE; t.w *= SCALE;
            qv0[i] = t;
            t = qp1[i];
            t.x *= SCALE; t.y *= SCALE; t.z *= SCALE; t.w *= SCALE;
            qv1[i] = t;
        }
    }

    float m0 = -INFINITY, l0 = 0.0f, m1 = -INFINITY, l1 = 0.0f;
    float4 acc0[8], acc1[8];
    #pragma unroll
    for (int i = 0; i < 8; i++) {
        acc0[i] = make_float4(0.f, 0.f, 0.f, 0.f);
        acc1[i] = make_float4(0.f, 0.f, 0.f, 0.f);
    }

    const float4* br0 = (const float4*)(g_bias + (size_t)q0 * LTOK);
    const float4* br1 = (const float4*)(g_bias + (size_t)q1 * LTOK);
    const int cg0 = kbeg >> 3;
    float4 b0A = br0[cg0 * 2], b0B = br0[cg0 * 2 + 1];
    float4 b1A = br1[cg0 * 2], b1B = br1[cg0 * 2 + 1];
    const int cgEnd = (kbeg + KEYS_PER_SPLIT) >> 3;

    #pragma unroll 1
    for (int t0 = kbeg; t0 < kbeg + KEYS_PER_SPLIT; t0 += 64) {
        #pragma unroll
        for (int i = tid; i < 512; i += 128) {
            const int r = i >> 3, d4 = i & 7;
            Ks[r][d4] = ((const float4*)(g_K + (size_t)(t0 + r) * DMODEL + head * HDIM))[d4];
            Vs[r][d4] = ((const float4*)(g_V + (size_t)(t0 + r) * DMODEL + head * HDIM))[d4];
        }
        __syncthreads();

        #pragma unroll 1
        for (int c = 0; c < 8; ++c) {
            const int cg = (t0 >> 3) + c + 1;  // next chunk (global index)
            float4 n0A = make_float4(0.f,0.f,0.f,0.f), n0B = n0A, n1A = n0A, n1B = n0A;
            if (cg < cgEnd) {
                n0A = br0[cg*2]; n0B = br0[cg*2+1];
                n1A = br1[cg*2]; n1B = br1[cg*2+1];
            }

            float s0[8] = { b0A.x, b0A.y, b0A.z, b0A.w, b0B.x, b0B.y, b0B.z, b0B.w };
            float s1[8] = { b1A.x, b1A.y, b1A.z, b1A.w, b1B.x, b1B.y, b1B.z, b1B.w };

            #pragma unroll
            for (int d4 = 0; d4 < 8; d4++) {
                const float4 qa = qv0[d4];
                const float4 qb = qv1[d4];
                #pragma unroll
                for (int j = 0; j < 8; j++) {
                    const float4 kk = Ks[c * 8 + j][d4];
                    s0[j] = fmaf(qa.w, kk.w,
                            fmaf(qa.z, kk.z,
                            fmaf(qa.y, kk.y,
                            fmaf(qa.x, kk.x, s0[j]))));
                    s1[j] = fmaf(qb.w, kk.w,
                            fmaf(qb.z, kk.z,
                            fmaf(qb.y, kk.y,
                            fmaf(qb.x, kk.x, s1[j]))));
                }
            }

            float cm0 = s0[0], cm1 = s1[0];
            #pragma unroll
            for (int j = 1; j < 8; j++) { cm0 = fmaxf(cm0, s0[j]); cm1 = fmaxf(cm1, s1[j]); }
            const float mn0 = fmaxf(m0, cm0);
            const float mn1 = fmaxf(m1, cm1);
            const float cr0 = __expf(m0 - mn0);
            const float cr1 = __expf(m1 - mn1);
            l0 *= cr0; l1 *= cr1;
            float p0[8], p1[8];
            #pragma unroll
            for (int j = 0; j < 8; j++) {
                p0[j] = __expf(s0[j] - mn0); l0 += p0[j];
                p1[j] = __expf(s1[j] - mn1); l1 += p1[j];
            }

            #pragma unroll
            for (int d4 = 0; d4 < 8; d4++) {
                float4 a0 = acc0[d4];
                float4 a1 = acc1[d4];
                a0.x *= cr0; a0.y *= cr0; a0.z *= cr0; a0.w *= cr0;
                a1.x *= cr1; a1.y *= cr1; a1.z *= cr1; a1.w *= cr1;
                #pragma unroll
                for (int j = 0; j < 8; j++) {
                    const float4 vv = Vs[c * 8 + j][d4];
                    a0.x = fmaf(p0[j], vv.x, a0.x);
                    a0.y = fmaf(p0[j], vv.y, a0.y);
                    a0.z = fmaf(p0[j], vv.z, a0.z);
                    a0.w = fmaf(p0[j], vv.w, a0.w);
                    a1.x = fmaf(p1[j], vv.x, a1.x);
                    a1.y = fmaf(p1[j], vv.y, a1.y);
                    a1.z = fmaf(p1[j], vv.z, a1.z);
                    a1.w = fmaf(p1[j], vv.w, a1.w);
                }
                acc0[d4] = a0;
                acc1[d4] = a1;
            }
            m0 = mn0; m1 = mn1;
            b0A = n0A; b0B = n0B; b1A = n1A; b1B = n1B;
        }
        __syncthreads();
    }

    const int row0 = head * LTOK + q0;
    const int row1 = head * LTOK + q1;
    float4* op0 = (float4*)(g_pacc + ((size_t)split * NROWS + row0) * HDIM);
    float4* op1 = (float4*)(g_pacc + ((size_t)split * NROWS + row1) * HDIM);
    #pragma unroll
    for (int d4 = 0; d4 < 8; d4++) { op0[d4] = acc0[d4]; op1[d4] = acc1[d4]; }
    g_pm[split * NROWS + row0] = m0;
    g_pl[split * NROWS + row0] = l0;
    g_pm[split * NROWS + row1] = m1;
    g_pl[split * NROWS + row1] = l1;
}

// ---------------------------------------------------------------------------------
// Merge split-K partials.
// ---------------------------------------------------------------------------------
__global__ void __launch_bounds__(256) merge_kernel()
{
    const int idx = blockIdx.x * 256 + threadIdx.x;
    const int row = idx >> 3, d4 = idx & 7;

    float mv[SPLIT];
    float mstar = -INFINITY;
    #pragma unroll
    for (int s = 0; s < SPLIT; s++) {
        mv[s] = g_pm[s * NROWS + row];
        mstar = fmaxf(mstar, mv[s]);
    }
    float denom = 0.0f;
    float4 o = make_float4(0.f, 0.f, 0.f, 0.f);
    #pragma unroll
    for (int s = 0; s < SPLIT; s++) {
        const float w = __expf(mv[s] - mstar);
        denom = fmaf(w, g_pl[s * NROWS + row], denom);
        const float4 a = *(const float4*)(g_pacc + ((size_t)s * NROWS + row) * HDIM + d4 * 4);
        o.x = fmaf(w, a.x, o.x);
        o.y = fmaf(w, a.y, o.y);
        o.z = fmaf(w, a.z, o.z);
        o.w = fmaf(w, a.w, o.w);
    }
    const float inv = 1.0f / denom;
    o.x *= inv; o.y *= inv; o.z *= inv; o.w *= inv;

    const int head = row >> 11, q = row & (LTOK - 1);
    *(float4*)(g_att + (size_t)q * DMODEL + head * HDIM + d4 * 4) = o;
}

// ---------------------------------------------------------------------------------
// LayerNorm over last dim (256). One block per row.
// ---------------------------------------------------------------------------------
__global__ void __launch_bounds__(256) ln_kernel(
    const float* __restrict__ y, const float* __restrict__ g,
    const float* __restrict__ b, float* __restrict__ out)
{
    __shared__ float red[16];
    const int row = blockIdx.x, t = threadIdx.x;
    const float v = y[row * DMODEL + t];

    float s = v;
    #pragma unroll
    for (int o = 16; o; o >>= 1) s += __shfl_xor_sync(0xffffffffu, s, o);
    if ((t & 31) == 0) red[t >> 5] = s;
    __syncthreads();
    float tot = 0.f;
    #pragma unroll
    for (int w = 0; w < 8; w++) tot += red[w];
    const float mu = tot * (1.0f / 256.0f);

    const float d = v - mu;
    float sq = d * d;
    #pragma unroll
    for (int o = 16; o; o >>= 1) sq += __shfl_xor_sync(0xffffffffu, sq, o);
    if ((t & 31) == 0) red[8 + (t >> 5)] = sq;
    __syncthreads();
    float tot2 = 0.f;
    #pragma unroll
    for (int w = 0; w < 8; w++) tot2 += red[8 + w];
    const float var = tot2 * (1.0f / 256.0f);

    out[row * DMODEL + t] = d * rsqrtf(var + LN_EPS) * g[t] + b[t];
}

// ---------------------------------------------------------------------------------
extern "C" void kernel_launch(void* const* d_in, const int* in_sizes, int n_in,
                              void* d_out, int out_size)
{
    const float* x    = (const float*)d_in[0];
    const float* pts  = (const float*)d_in[1];
    const float* Wq   = (const float*)d_in[2];
    const float* bq   = (const float*)d_in[3];
    const float* Wk   = (const float*)d_in[4];
    const float* bk   = (const float*)d_in[5];
    const float* Wv   = (const float*)d_in[6];
    const float* bv   = (const float*)d_in[7];
    const float* Wo   = (const float*)d_in[8];
    const float* bo   = (const float*)d_in[9];
    const float* beta = (const float*)d_in[10];
    const float* kw1  = (const float*)d_in[11];
    const float* kb1  = (const float*)d_in[12];
    const float* kw2  = (const float*)d_in[13];
    const float* kb2  = (const float*)d_in[14];
    const float* lng  = (const float*)d_in[15];
    const float* lnb  = (const float*)d_in[16];
    float* out = (float*)d_out;

    float *Qb, *Kb, *Vb, *Ab, *Pb;
    cudaGetSymbolAddress((void**)&Qb, g_Q);
    cudaGetSymbolAddress((void**)&Kb, g_K);
    cudaGetSymbolAddress((void**)&Vb, g_V);
    cudaGetSymbolAddress((void**)&Ab, g_att);
    cudaGetSymbolAddress((void**)&Pb, g_proj);

    setup_geo_tables<<<1, 1>>>(kw1, kb1, kw2, kb2);

    gemm_qkv<<<dim3(DMODEL/64, LTOK/64, 3), 256>>>(x, Wq, bq, Wk, bk, Wv, bv, Qb, Kb, Vb);

    geo_bias_kernel<<<LTOK / 4, 256>>>(pts, beta);

    attn_kernel<<<NHEADS * 8 * SPLIT, 128>>>();
    merge_kernel<<<NROWS * 8 / 256, 256>>>();

    gemm_o<<<dim3(DMODEL/64, LTOK/64), 256>>>(Ab, Wo, bo, x, Pb);

    ln_kernel<<<LTOK, 256>>>(Pb, lng, lnb, out);
}

// round 4
// speedup vs baseline: 1.7401x; 1.3145x over previous
#include <cuda_runtime.h>
#include <math.h>
#include <stdint.h>

#define LTOK 2048
#define DMODEL 256
#define NHEADS 8
#define HDIM 32
#define SCALE 0.17677669529663687f  /* 32^-0.5 */
#define LN_EPS 1e-5f

// ---------------- scratch (device globals; no allocation allowed) ----------------
__device__ float g_Q[LTOK * DMODEL];
__device__ float g_K[LTOK * DMODEL];
__device__ float g_V[LTOK * DMODEL];
__device__ float g_bias[LTOK * LTOK];     // beta * clip(bias), head-independent
__device__ float g_att[LTOK * DMODEL];    // attention output pre-projection
__device__ float g_proj[LTOK * DMODEL];   // x + attn @ Wo^T + bo
// piecewise-linear tables for the geometric-bias MLP
__device__ float g_T[32];   // sorted thresholds (padded +INF)
__device__ float g_S[33];   // prefix slopes
__device__ float g_C[33];   // prefix intercepts

// ---------------------------------------------------------------------------------
// tf32 helpers
// ---------------------------------------------------------------------------------
__device__ __forceinline__ uint32_t f2tf(float x) {
    uint32_t u;
    asm("cvt.rna.tf32.f32 %0, %1;" : "=r"(u) : "f"(x));
    return u;
}

__device__ __forceinline__ void mma_tf32(float c[4], const uint32_t a[4],
                                         uint32_t b0, uint32_t b1) {
    asm volatile(
        "mma.sync.aligned.m16n8k8.row.col.f32.tf32.tf32.f32 "
        "{%0,%1,%2,%3}, {%4,%5,%6,%7}, {%8,%9}, {%0,%1,%2,%3};\n"
        : "+f"(c[0]), "+f"(c[1]), "+f"(c[2]), "+f"(c[3])
        : "r"(a[0]), "r"(a[1]), "r"(a[2]), "r"(a[3]), "r"(b0), "r"(b1));
}

// ---------------------------------------------------------------------------------
// GEMM: C[m][n] = sum_k A[m][k] * W[n][k] + bias[n] (+ resid). 64x64x16, 4x4/thread.
// ---------------------------------------------------------------------------------
__device__ __forceinline__ void gemm_body(
    const float* __restrict__ A, const float* __restrict__ W,
    const float* __restrict__ bias, const float* __restrict__ resid,
    float* __restrict__ C, int K, int N,
    float As[16][68], float Bs[16][68])
{
    const int tid = threadIdx.x;
    const int tx = tid & 15, ty = tid >> 4;
    const int m0 = blockIdx.y * 64, n0 = blockIdx.x * 64;

    const int lm = tid >> 2;
    const int lk = (tid & 3) << 2;
    const float* Ab = A + (m0 + lm) * K + lk;
    const float* Wb = W + (n0 + lm) * K + lk;

    float acc[4][4] = {};

    for (int k0 = 0; k0 < K; k0 += 16) {
        float4 av = *(const float4*)(Ab + k0);
        float4 wv = *(const float4*)(Wb + k0);
        As[lk + 0][lm] = av.x; As[lk + 1][lm] = av.y;
        As[lk + 2][lm] = av.z; As[lk + 3][lm] = av.w;
        Bs[lk + 0][lm] = wv.x; Bs[lk + 1][lm] = wv.y;
        Bs[lk + 2][lm] = wv.z; Bs[lk + 3][lm] = wv.w;
        __syncthreads();
        #pragma unroll
        for (int kk = 0; kk < 16; kk++) {
            float a[4], b[4];
            #pragma unroll
            for (int i = 0; i < 4; i++) a[i] = As[kk][ty * 4 + i];
            #pragma unroll
            for (int j = 0; j < 4; j++) b[j] = Bs[kk][tx * 4 + j];
            #pragma unroll
            for (int i = 0; i < 4; i++)
                #pragma unroll
                for (int j = 0; j < 4; j++)
                    acc[i][j] = fmaf(a[i], b[j], acc[i][j]);
        }
        __syncthreads();
    }

    #pragma unroll
    for (int i = 0; i < 4; i++) {
        const int m = m0 + ty * 4 + i;
        #pragma unroll
        for (int j = 0; j < 4; j++) {
            const int n = n0 + tx * 4 + j;
            float v = acc[i][j] + bias[n];
            if (resid) v += resid[m * N + n];
            C[m * N + n] = v;
        }
    }
}

__global__ void __launch_bounds__(256) gemm_qkv(
    const float* __restrict__ x,
    const float* __restrict__ Wq, const float* __restrict__ bq,
    const float* __restrict__ Wk, const float* __restrict__ bk,
    const float* __restrict__ Wv, const float* __restrict__ bv,
    float* __restrict__ Qo, float* __restrict__ Ko, float* __restrict__ Vo)
{
    __shared__ float As[16][68];
    __shared__ float Bs[16][68];
    const float* W; const float* b; float* C;
    if (blockIdx.z == 0)      { W = Wq; b = bq; C = Qo; }
    else if (blockIdx.z == 1) { W = Wk; b = bk; C = Ko; }
    else                      { W = Wv; b = bv; C = Vo; }
    gemm_body(x, W, b, nullptr, C, DMODEL, DMODEL, As, Bs);
}

__global__ void __launch_bounds__(256) gemm_o(
    const float* __restrict__ A, const float* __restrict__ W,
    const float* __restrict__ b, const float* __restrict__ resid,
    float* __restrict__ C)
{
    __shared__ float As[16][68];
    __shared__ float Bs[16][68];
    gemm_body(A, W, b, resid, C, DMODEL, DMODEL, As, Bs);
}

// ---------------------------------------------------------------------------------
// Setup: bias MLP is piecewise-linear in d; build threshold/prefix tables. 1 thread.
// ---------------------------------------------------------------------------------
__global__ void setup_geo_tables(
    const float* __restrict__ kw1, const float* __restrict__ kb1,
    const float* __restrict__ kw2, const float* __restrict__ kb2)
{
    float t[32], ds[32], dc[32];
    int n = 0;
    float S0 = 0.0f, C0 = kb2[0];
    for (int j = 0; j < 32; j++) {
        const float w1 = kw1[j], b1 = kb1[j], w2 = kw2[j];
        if (b1 > 0.0f) { S0 += w1 * w2; C0 += b1 * w2; }
        if (w1 > 0.0f && !(b1 > 0.0f)) {
            t[n] = -b1 / w1; ds[n] = w1 * w2; dc[n] = b1 * w2; n++;
        } else if (w1 < 0.0f && b1 > 0.0f) {
            t[n] = -b1 / w1; ds[n] = -w1 * w2; dc[n] = -b1 * w2; n++;
        }
    }
    for (int i = 1; i < n; i++) {
        float tv = t[i], sv = ds[i], cv = dc[i];
        int j = i - 1;
        while (j >= 0 && t[j] > tv) { t[j+1]=t[j]; ds[j+1]=ds[j]; dc[j+1]=dc[j]; j--; }
        t[j+1] = tv; ds[j+1] = sv; dc[j+1] = cv;
    }
    g_S[0] = S0; g_C[0] = C0;
    for (int i = 0; i < 32; i++) {
        if (i < n) {
            g_T[i] = t[i];
            g_S[i+1] = g_S[i] + ds[i];
            g_C[i+1] = g_C[i] + dc[i];
        } else {
            g_T[i] = INFINITY;
            g_S[i+1] = g_S[i];
            g_C[i+1] = g_C[i];
        }
    }
}

// ---------------------------------------------------------------------------------
// Geometric bias via table lookup. 512 blocks x 4 query rows, 256 threads.
// ---------------------------------------------------------------------------------
__global__ void __launch_bounds__(256) geo_bias_kernel(
    const float* __restrict__ pts, const float* __restrict__ beta)
{
    __shared__ float sp[LTOK * 3];
    __shared__ float sT[32], sS[33], sC[33];
    const int tid = threadIdx.x;
    for (int i = tid; i < LTOK * 3; i += 256) sp[i] = pts[i];
    if (tid < 32) sT[tid] = g_T[tid];
    if (tid < 33) { sS[tid] = g_S[tid]; sC[tid] = g_C[tid]; }
    __syncthreads();

    const float bet = beta[0];
    const int qbase = blockIdx.x * 4;

    #pragma unroll
    for (int qi = 0; qi < 4; qi++) {
        const int q = qbase + qi;
        const float qx = sp[q*3+0], qy = sp[q*3+1], qz = sp[q*3+2];
        for (int k = tid; k < LTOK; k += 256) {
            const float dx = qx - sp[k*3+0];
            const float dy = qy - sp[k*3+1];
            const float dz = qz - sp[k*3+2];
            const float d = sqrtf(dx*dx + dy*dy + dz*dz);
            int i = 0;
            #pragma unroll
            for (int s = 16; s; s >>= 1) if (sT[i + s - 1] < d) i += s;
            const float b = fmaf(sS[i], d, sC[i]);
            g_bias[q * LTOK + k] = bet * fminf(fmaxf(b, -10.0f), 0.0f);
        }
    }
}

// ---------------------------------------------------------------------------------
// tf32 mma.sync flash attention.
// CTA: 128 threads / 4 warps / 64 queries (16 q per warp). Full 2048-key loop in
// 64-key tiles. Grid = 8 heads * 32 qtiles = 256 CTAs.
// smem pads chosen so all fragment LDS patterns are bank-conflict-free.
// ---------------------------------------------------------------------------------
__global__ void __launch_bounds__(128) attn_kernel()
{
    __shared__ uint32_t Ks[64][36];      // K tile [key][d], tf32 bits
    __shared__ uint32_t Vt[32][68];      // V tile transposed [d][key], tf32 bits
    __shared__ uint32_t Ps[4][16][68];   // per-warp P tile [q][key], tf32 bits

    const int tid  = threadIdx.x;
    const int warp = tid >> 5;
    const int lane = tid & 31;
    const int g  = lane >> 2;   // 0..7
    const int tg = lane & 3;    // 0..3

    const int head  = blockIdx.x >> 5;
    const int qtile = blockIdx.x & 31;
    const int qw = qtile * 64 + warp * 16;   // warp's query base

    // Q fragments: 4 k-steps (d-chunks of 8), 4 regs each, pre-scaled
    uint32_t qf[4][4];
    {
        const float* Qb = g_Q + (size_t)(qw) * DMODEL + head * HDIM;
        #pragma unroll
        for (int ks = 0; ks < 4; ks++) {
            qf[ks][0] = f2tf(SCALE * Qb[(g    ) * DMODEL + ks*8 + tg    ]);
            qf[ks][1] = f2tf(SCALE * Qb[(g + 8) * DMODEL + ks*8 + tg    ]);
            qf[ks][2] = f2tf(SCALE * Qb[(g    ) * DMODEL + ks*8 + tg + 4]);
            qf[ks][3] = f2tf(SCALE * Qb[(g + 8) * DMODEL + ks*8 + tg + 4]);
        }
    }

    float o[4][4];
    #pragma unroll
    for (int nt = 0; nt < 4; nt++)
        #pragma unroll
        for (int j = 0; j < 4; j++) o[nt][j] = 0.0f;
    float m0 = -INFINITY, m1 = -INFINITY, l0 = 0.0f, l1 = 0.0f;

    const float* b0p = g_bias + (size_t)(qw + g) * LTOK + 2 * tg;
    const float* b1p = b0p + 8 * LTOK;

    uint32_t (*Pw)[68] = Ps[warp];

    #pragma unroll 1
    for (int t0 = 0; t0 < LTOK; t0 += 64) {
        // ---- stage K/V tile (K as [key][d], V transposed to [d][key]) ----
        #pragma unroll
        for (int i = tid; i < 512; i += 128) {
            const int r  = i >> 3;
            const int d4 = (i & 7) << 2;
            float4 kv = *(const float4*)(g_K + (size_t)(t0 + r) * DMODEL + head * HDIM + d4);
            *(uint4*)&Ks[r][d4] = make_uint4(f2tf(kv.x), f2tf(kv.y), f2tf(kv.z), f2tf(kv.w));
            float4 vv = *(const float4*)(g_V + (size_t)(t0 + r) * DMODEL + head * HDIM + d4);
            Vt[d4 + 0][r] = f2tf(vv.x);
            Vt[d4 + 1][r] = f2tf(vv.y);
            Vt[d4 + 2][r] = f2tf(vv.z);
            Vt[d4 + 3][r] = f2tf(vv.w);
        }
        __syncthreads();

        // ---- scores: S = Q K^T + bias (bias seeds the accumulators) ----
        float s[8][4];
        #pragma unroll
        for (int nt = 0; nt < 8; nt++) {
            float2 bb0 = *(const float2*)(b0p + t0 + nt * 8);
            float2 bb1 = *(const float2*)(b1p + t0 + nt * 8);
            s[nt][0] = bb0.x; s[nt][1] = bb0.y;
            s[nt][2] = bb1.x; s[nt][3] = bb1.y;
            #pragma unroll
            for (int ks = 0; ks < 4; ks++) {
                const uint32_t kb0 = Ks[nt * 8 + g][ks * 8 + tg];
                const uint32_t kb1 = Ks[nt * 8 + g][ks * 8 + tg + 4];
                mma_tf32(s[nt], qf[ks], kb0, kb1);
            }
        }

        // ---- online softmax (rows g and g+8; quad shfl for row reduce) ----
        float mx0 = -INFINITY, mx1 = -INFINITY;
        #pragma unroll
        for (int nt = 0; nt < 8; nt++) {
            mx0 = fmaxf(mx0, fmaxf(s[nt][0], s[nt][1]));
            mx1 = fmaxf(mx1, fmaxf(s[nt][2], s[nt][3]));
        }
        mx0 = fmaxf(mx0, __shfl_xor_sync(0xffffffffu, mx0, 1));
        mx0 = fmaxf(mx0, __shfl_xor_sync(0xffffffffu, mx0, 2));
        mx1 = fmaxf(mx1, __shfl_xor_sync(0xffffffffu, mx1, 1));
        mx1 = fmaxf(mx1, __shfl_xor_sync(0xffffffffu, mx1, 2));

        const float mn0 = fmaxf(m0, mx0);
        const float mn1 = fmaxf(m1, mx1);
        const float cr0 = __expf(m0 - mn0);
        const float cr1 = __expf(m1 - mn1);

        float sum0 = 0.0f, sum1 = 0.0f;
        #pragma unroll
        for (int nt = 0; nt < 8; nt++) {
            const float p0 = __expf(s[nt][0] - mn0);
            const float p1 = __expf(s[nt][1] - mn0);
            const float p2 = __expf(s[nt][2] - mn1);
            const float p3 = __expf(s[nt][3] - mn1);
            sum0 += p0 + p1;
            sum1 += p2 + p3;
            *(uint2*)&Pw[g    ][nt * 8 + 2 * tg] = make_uint2(f2tf(p0), f2tf(p1));
            *(uint2*)&Pw[g + 8][nt * 8 + 2 * tg] = make_uint2(f2tf(p2), f2tf(p3));
        }
        sum0 += __shfl_xor_sync(0xffffffffu, sum0, 1);
        sum0 += __shfl_xor_sync(0xffffffffu, sum0, 2);
        sum1 += __shfl_xor_sync(0xffffffffu, sum1, 1);
        sum1 += __shfl_xor_sync(0xffffffffu, sum1, 2);

        l0 = l0 * cr0 + sum0;
        l1 = l1 * cr1 + sum1;
        m0 = mn0;
        m1 = mn1;

        #pragma unroll
        for (int nt = 0; nt < 4; nt++) {
            o[nt][0] *= cr0; o[nt][1] *= cr0;
            o[nt][2] *= cr1; o[nt][3] *= cr1;
        }
        __syncwarp();

        // ---- O += P V ----
        #pragma unroll
        for (int ks = 0; ks < 8; ks++) {
            uint32_t a[4];
            a[0] = Pw[g    ][ks * 8 + tg];
            a[1] = Pw[g + 8][ks * 8 + tg];
            a[2] = Pw[g    ][ks * 8 + tg + 4];
            a[3] = Pw[g + 8][ks * 8 + tg + 4];
            #pragma unroll
            for (int nt = 0; nt < 4; nt++) {
                mma_tf32(o[nt], a, Vt[nt * 8 + g][ks * 8 + tg],
                                   Vt[nt * 8 + g][ks * 8 + tg + 4]);
            }
        }
        __syncthreads();
    }

    // ---- normalize + store ----
    const float inv0 = 1.0f / l0;
    const float inv1 = 1.0f / l1;
    float* Ob = g_att + head * HDIM + 2 * tg;
    #pragma unroll
    for (int nt = 0; nt < 4; nt++) {
        *(float2*)(Ob + (size_t)(qw + g    ) * DMODEL + nt * 8) =
            make_float2(o[nt][0] * inv0, o[nt][1] * inv0);
        *(float2*)(Ob + (size_t)(qw + g + 8) * DMODEL + nt * 8) =
            make_float2(o[nt][2] * inv1, o[nt][3] * inv1);
    }
}

// ---------------------------------------------------------------------------------
// LayerNorm over last dim (256). One block per row.
// ---------------------------------------------------------------------------------
__global__ void __launch_bounds__(256) ln_kernel(
    const float* __restrict__ y, const float* __restrict__ g,
    const float* __restrict__ b, float* __restrict__ out)
{
    __shared__ float red[16];
    const int row = blockIdx.x, t = threadIdx.x;
    const float v = y[row * DMODEL + t];

    float s = v;
    #pragma unroll
    for (int o = 16; o; o >>= 1) s += __shfl_xor_sync(0xffffffffu, s, o);
    if ((t & 31) == 0) red[t >> 5] = s;
    __syncthreads();
    float tot = 0.f;
    #pragma unroll
    for (int w = 0; w < 8; w++) tot += red[w];
    const float mu = tot * (1.0f / 256.0f);

    const float d = v - mu;
    float sq = d * d;
    #pragma unroll
    for (int o = 16; o; o >>= 1) sq += __shfl_xor_sync(0xffffffffu, sq, o);
    if ((t & 31) == 0) red[8 + (t >> 5)] = sq;
    __syncthreads();
    float tot2 = 0.f;
    #pragma unroll
    for (int w = 0; w < 8; w++) tot2 += red[8 + w];
    const float var = tot2 * (1.0f / 256.0f);

    out[row * DMODEL + t] = d * rsqrtf(var + LN_EPS) * g[t] + b[t];
}

// ---------------------------------------------------------------------------------
extern "C" void kernel_launch(void* const* d_in, const int* in_sizes, int n_in,
                              void* d_out, int out_size)
{
    const float* x    = (const float*)d_in[0];
    const float* pts  = (const float*)d_in[1];
    const float* Wq   = (const float*)d_in[2];
    const float* bq   = (const float*)d_in[3];
    const float* Wk   = (const float*)d_in[4];
    const float* bk   = (const float*)d_in[5];
    const float* Wv   = (const float*)d_in[6];
    const float* bv   = (const float*)d_in[7];
    const float* Wo   = (const float*)d_in[8];
    const float* bo   = (const float*)d_in[9];
    const float* beta = (const float*)d_in[10];
    const float* kw1  = (const float*)d_in[11];
    const float* kb1  = (const float*)d_in[12];
    const float* kw2  = (const float*)d_in[13];
    const float* kb2  = (const float*)d_in[14];
    const float* lng  = (const float*)d_in[15];
    const float* lnb  = (const float*)d_in[16];
    float* out = (float*)d_out;

    float *Qb, *Kb, *Vb, *Ab, *Pb;
    cudaGetSymbolAddress((void**)&Qb, g_Q);
    cudaGetSymbolAddress((void**)&Kb, g_K);
    cudaGetSymbolAddress((void**)&Vb, g_V);
    cudaGetSymbolAddress((void**)&Ab, g_att);
    cudaGetSymbolAddress((void**)&Pb, g_proj);

    setup_geo_tables<<<1, 1>>>(kw1, kb1, kw2, kb2);

    gemm_qkv<<<dim3(DMODEL/64, LTOK/64, 3), 256>>>(x, Wq, bq, Wk, bk, Wv, bv, Qb, Kb, Vb);

    geo_bias_kernel<<<LTOK / 4, 256>>>(pts, beta);

    attn_kernel<<<NHEADS * 32, 128>>>();

    gemm_o<<<dim3(DMODEL/64, LTOK/64), 256>>>(Ab, Wo, bo, x, Pb);

    ln_kernel<<<LTOK, 256>>>(Pb, lng, lnb, out);
}

// round 5
// speedup vs baseline: 1.9725x; 1.1336x over previous
#include <cuda_runtime.h>
#include <math.h>
#include <stdint.h>

#define LTOK 2048
#define DMODEL 256
#define NHEADS 8
#define HDIM 32
#define SCALE 0.17677669529663687f  /* 32^-0.5 */
#define LN_EPS 1e-5f
#define SPLIT 4
#define KEYS_PER_SPLIT (LTOK / SPLIT)   /* 512 */
#define NROWS (NHEADS * LTOK)           /* 16384 */

// ---------------- scratch (device globals; no allocation allowed) ----------------
__device__ float g_Q[LTOK * DMODEL];
__device__ float g_K[LTOK * DMODEL];
__device__ float g_V[LTOK * DMODEL];
__device__ float g_bias[LTOK * LTOK];     // beta * clip(bias), head-independent
__device__ float g_att[LTOK * DMODEL];    // attention output pre-projection
__device__ float g_proj[LTOK * DMODEL];   // x + attn @ Wo^T + bo
__device__ float g_pacc[SPLIT * NROWS * HDIM]; // split-K partials (unnormalized)
__device__ float g_pm[SPLIT * NROWS];
__device__ float g_pl[SPLIT * NROWS];
// piecewise-linear tables for the geometric-bias MLP
__device__ float g_T[32];
__device__ float g_S[33];
__device__ float g_C[33];

// ---------------------------------------------------------------------------------
// tf32 helpers
// ---------------------------------------------------------------------------------
__device__ __forceinline__ uint32_t f2tf(float x) {
    uint32_t u;
    asm("cvt.rna.tf32.f32 %0, %1;" : "=r"(u) : "f"(x));
    return u;
}

__device__ __forceinline__ void mma_tf32(float c[4], const uint32_t a[4],
                                         uint32_t b0, uint32_t b1) {
    asm volatile(
        "mma.sync.aligned.m16n8k8.row.col.f32.tf32.tf32.f32 "
        "{%0,%1,%2,%3}, {%4,%5,%6,%7}, {%8,%9}, {%0,%1,%2,%3};\n"
        : "+f"(c[0]), "+f"(c[1]), "+f"(c[2]), "+f"(c[3])
        : "r"(a[0]), "r"(a[1]), "r"(a[2]), "r"(a[3]), "r"(b0), "r"(b1));
}

// ---------------------------------------------------------------------------------
// GEMM: C[m][n] = sum_k A[m][k] * W[n][k] + bias[n] (+ resid). 64x64x16, 4x4/thread.
// ---------------------------------------------------------------------------------
__device__ __forceinline__ void gemm_body(
    const float* __restrict__ A, const float* __restrict__ W,
    const float* __restrict__ bias, const float* __restrict__ resid,
    float* __restrict__ C, int K, int N,
    float As[16][68], float Bs[16][68])
{
    const int tid = threadIdx.x;
    const int tx = tid & 15, ty = tid >> 4;
    const int m0 = blockIdx.y * 64, n0 = blockIdx.x * 64;

    const int lm = tid >> 2;
    const int lk = (tid & 3) << 2;
    const float* Ab = A + (m0 + lm) * K + lk;
    const float* Wb = W + (n0 + lm) * K + lk;

    float acc[4][4] = {};

    for (int k0 = 0; k0 < K; k0 += 16) {
        float4 av = *(const float4*)(Ab + k0);
        float4 wv = *(const float4*)(Wb + k0);
        As[lk + 0][lm] = av.x; As[lk + 1][lm] = av.y;
        As[lk + 2][lm] = av.z; As[lk + 3][lm] = av.w;
        Bs[lk + 0][lm] = wv.x; Bs[lk + 1][lm] = wv.y;
        Bs[lk + 2][lm] = wv.z; Bs[lk + 3][lm] = wv.w;
        __syncthreads();
        #pragma unroll
        for (int kk = 0; kk < 16; kk++) {
            float a[4], b[4];
            #pragma unroll
            for (int i = 0; i < 4; i++) a[i] = As[kk][ty * 4 + i];
            #pragma unroll
            for (int j = 0; j < 4; j++) b[j] = Bs[kk][tx * 4 + j];
            #pragma unroll
            for (int i = 0; i < 4; i++)
                #pragma unroll
                for (int j = 0; j < 4; j++)
                    acc[i][j] = fmaf(a[i], b[j], acc[i][j]);
        }
        __syncthreads();
    }

    #pragma unroll
    for (int i = 0; i < 4; i++) {
        const int m = m0 + ty * 4 + i;
        #pragma unroll
        for (int j = 0; j < 4; j++) {
            const int n = n0 + tx * 4 + j;
            float v = acc[i][j] + bias[n];
            if (resid) v += resid[m * N + n];
            C[m * N + n] = v;
        }
    }
}

__global__ void __launch_bounds__(256) gemm_qkv(
    const float* __restrict__ x,
    const float* __restrict__ Wq, const float* __restrict__ bq,
    const float* __restrict__ Wk, const float* __restrict__ bk,
    const float* __restrict__ Wv, const float* __restrict__ bv,
    float* __restrict__ Qo, float* __restrict__ Ko, float* __restrict__ Vo)
{
    __shared__ float As[16][68];
    __shared__ float Bs[16][68];
    const float* W; const float* b; float* C;
    if (blockIdx.z == 0)      { W = Wq; b = bq; C = Qo; }
    else if (blockIdx.z == 1) { W = Wk; b = bk; C = Ko; }
    else                      { W = Wv; b = bv; C = Vo; }
    gemm_body(x, W, b, nullptr, C, DMODEL, DMODEL, As, Bs);
}

__global__ void __launch_bounds__(256) gemm_o(
    const float* __restrict__ A, const float* __restrict__ W,
    const float* __restrict__ b, const float* __restrict__ resid,
    float* __restrict__ C)
{
    __shared__ float As[16][68];
    __shared__ float Bs[16][68];
    gemm_body(A, W, b, resid, C, DMODEL, DMODEL, As, Bs);
}

// ---------------------------------------------------------------------------------
// Setup: bias MLP is piecewise-linear in d; build threshold/prefix tables. 1 thread.
// ---------------------------------------------------------------------------------
__global__ void setup_geo_tables(
    const float* __restrict__ kw1, const float* __restrict__ kb1,
    const float* __restrict__ kw2, const float* __restrict__ kb2)
{
    float t[32], ds[32], dc[32];
    int n = 0;
    float S0 = 0.0f, C0 = kb2[0];
    for (int j = 0; j < 32; j++) {
        const float w1 = kw1[j], b1 = kb1[j], w2 = kw2[j];
        if (b1 > 0.0f) { S0 += w1 * w2; C0 += b1 * w2; }
        if (w1 > 0.0f && !(b1 > 0.0f)) {
            t[n] = -b1 / w1; ds[n] = w1 * w2; dc[n] = b1 * w2; n++;
        } else if (w1 < 0.0f && b1 > 0.0f) {
            t[n] = -b1 / w1; ds[n] = -w1 * w2; dc[n] = -b1 * w2; n++;
        }
    }
    for (int i = 1; i < n; i++) {
        float tv = t[i], sv = ds[i], cv = dc[i];
        int j = i - 1;
        while (j >= 0 && t[j] > tv) { t[j+1]=t[j]; ds[j+1]=ds[j]; dc[j+1]=dc[j]; j--; }
        t[j+1] = tv; ds[j+1] = sv; dc[j+1] = cv;
    }
    g_S[0] = S0; g_C[0] = C0;
    for (int i = 0; i < 32; i++) {
        if (i < n) {
            g_T[i] = t[i];
            g_S[i+1] = g_S[i] + ds[i];
            g_C[i+1] = g_C[i] + dc[i];
        } else {
            g_T[i] = INFINITY;
            g_S[i+1] = g_S[i];
            g_C[i+1] = g_C[i];
        }
    }
}

// ---------------------------------------------------------------------------------
// Geometric bias via table lookup. 512 blocks x 4 query rows, 256 threads.
// ---------------------------------------------------------------------------------
__global__ void __launch_bounds__(256) geo_bias_kernel(
    const float* __restrict__ pts, const float* __restrict__ beta)
{
    __shared__ float sp[LTOK * 3];
    __shared__ float sT[32], sS[33], sC[33];
    const int tid = threadIdx.x;
    for (int i = tid; i < LTOK * 3; i += 256) sp[i] = pts[i];
    if (tid < 32) sT[tid] = g_T[tid];
    if (tid < 33) { sS[tid] = g_S[tid]; sC[tid] = g_C[tid]; }
    __syncthreads();

    const float bet = beta[0];
    const int qbase = blockIdx.x * 4;

    #pragma unroll
    for (int qi = 0; qi < 4; qi++) {
        const int q = qbase + qi;
        const float qx = sp[q*3+0], qy = sp[q*3+1], qz = sp[q*3+2];
        for (int k = tid; k < LTOK; k += 256) {
            const float dx = qx - sp[k*3+0];
            const float dy = qy - sp[k*3+1];
            const float dz = qz - sp[k*3+2];
            const float d = sqrtf(dx*dx + dy*dy + dz*dz);
            int i = 0;
            #pragma unroll
            for (int s = 16; s; s >>= 1) if (sT[i + s - 1] < d) i += s;
            const float b = fmaf(sS[i], d, sC[i]);
            g_bias[q * LTOK + k] = bet * fminf(fmaxf(b, -10.0f), 0.0f);
        }
    }
}

// ---------------------------------------------------------------------------------
// tf32 mma.sync flash attention, SPLIT-K x4.
// CTA: 128 threads / 4 warps / 64 queries (16 q per warp); 512 keys per CTA.
// Grid = 8 heads * 32 qtiles * 4 splits = 1024 CTAs.
// ---------------------------------------------------------------------------------
__global__ void __launch_bounds__(128) attn_kernel()
{
    __shared__ uint32_t Ks[64][36];      // K tile [key][d], tf32 bits
    __shared__ uint32_t Vt[32][68];      // V tile transposed [d][key], tf32 bits
    __shared__ uint32_t Ps[4][16][68];   // per-warp P tile [q][key], tf32 bits

    const int tid  = threadIdx.x;
    const int warp = tid >> 5;
    const int lane = tid & 31;
    const int g  = lane >> 2;   // 0..7
    const int tg = lane & 3;    // 0..3

    const int split = blockIdx.x & (SPLIT - 1);
    const int qtile = (blockIdx.x >> 2) & 31;
    const int head  = blockIdx.x >> 7;
    const int qw = qtile * 64 + warp * 16;   // warp's query base
    const int kbeg = split * KEYS_PER_SPLIT;

    // Q fragments: 4 k-steps (d-chunks of 8), 4 regs each, pre-scaled
    uint32_t qf[4][4];
    {
        const float* Qb = g_Q + (size_t)(qw) * DMODEL + head * HDIM;
        #pragma unroll
        for (int ks = 0; ks < 4; ks++) {
            qf[ks][0] = f2tf(SCALE * Qb[(g    ) * DMODEL + ks*8 + tg    ]);
            qf[ks][1] = f2tf(SCALE * Qb[(g + 8) * DMODEL + ks*8 + tg    ]);
            qf[ks][2] = f2tf(SCALE * Qb[(g    ) * DMODEL + ks*8 + tg + 4]);
            qf[ks][3] = f2tf(SCALE * Qb[(g + 8) * DMODEL + ks*8 + tg + 4]);
        }
    }

    float o[4][4];
    #pragma unroll
    for (int nt = 0; nt < 4; nt++)
        #pragma unroll
        for (int j = 0; j < 4; j++) o[nt][j] = 0.0f;
    float m0 = -INFINITY, m1 = -INFINITY, l0 = 0.0f, l1 = 0.0f;

    const float* b0p = g_bias + (size_t)(qw + g) * LTOK + 2 * tg;
    const float* b1p = b0p + 8 * LTOK;

    uint32_t (*Pw)[68] = Ps[warp];

    #pragma unroll 1
    for (int t0 = kbeg; t0 < kbeg + KEYS_PER_SPLIT; t0 += 64) {
        // ---- stage K/V tile (K as [key][d], V transposed to [d][key]) ----
        #pragma unroll
        for (int i = tid; i < 512; i += 128) {
            const int r  = i >> 3;
            const int d4 = (i & 7) << 2;
            float4 kv = *(const float4*)(g_K + (size_t)(t0 + r) * DMODEL + head * HDIM + d4);
            *(uint4*)&Ks[r][d4] = make_uint4(f2tf(kv.x), f2tf(kv.y), f2tf(kv.z), f2tf(kv.w));
            float4 vv = *(const float4*)(g_V + (size_t)(t0 + r) * DMODEL + head * HDIM + d4);
            Vt[d4 + 0][r] = f2tf(vv.x);
            Vt[d4 + 1][r] = f2tf(vv.y);
            Vt[d4 + 2][r] = f2tf(vv.z);
            Vt[d4 + 3][r] = f2tf(vv.w);
        }
        __syncthreads();

        // ---- scores: S = Q K^T + bias (bias seeds the accumulators) ----
        float s[8][4];
        #pragma unroll
        for (int nt = 0; nt < 8; nt++) {
            float2 bb0 = *(const float2*)(b0p + t0 + nt * 8);
            float2 bb1 = *(const float2*)(b1p + t0 + nt * 8);
            s[nt][0] = bb0.x; s[nt][1] = bb0.y;
            s[nt][2] = bb1.x; s[nt][3] = bb1.y;
            #pragma unroll
            for (int ks = 0; ks < 4; ks++) {
                const uint32_t kb0 = Ks[nt * 8 + g][ks * 8 + tg];
                const uint32_t kb1 = Ks[nt * 8 + g][ks * 8 + tg + 4];
                mma_tf32(s[nt], qf[ks], kb0, kb1);
            }
        }

        // ---- online softmax (rows g and g+8; quad shfl for row reduce) ----
        float mx0 = -INFINITY, mx1 = -INFINITY;
        #pragma unroll
        for (int nt = 0; nt < 8; nt++) {
            mx0 = fmaxf(mx0, fmaxf(s[nt][0], s[nt][1]));
            mx1 = fmaxf(mx1, fmaxf(s[nt][2], s[nt][3]));
        }
        mx0 = fmaxf(mx0, __shfl_xor_sync(0xffffffffu, mx0, 1));
        mx0 = fmaxf(mx0, __shfl_xor_sync(0xffffffffu, mx0, 2));
        mx1 = fmaxf(mx1, __shfl_xor_sync(0xffffffffu, mx1, 1));
        mx1 = fmaxf(mx1, __shfl_xor_sync(0xffffffffu, mx1, 2));

        const float mn0 = fmaxf(m0, mx0);
        const float mn1 = fmaxf(m1, mx1);
        const float cr0 = __expf(m0 - mn0);
        const float cr1 = __expf(m1 - mn1);

        float sum0 = 0.0f, sum1 = 0.0f;
        #pragma unroll
        for (int nt = 0; nt < 8; nt++) {
            const float p0 = __expf(s[nt][0] - mn0);
            const float p1 = __expf(s[nt][1] - mn0);
            const float p2 = __expf(s[nt][2] - mn1);
            const float p3 = __expf(s[nt][3] - mn1);
            sum0 += p0 + p1;
            sum1 += p2 + p3;
            *(uint2*)&Pw[g    ][nt * 8 + 2 * tg] = make_uint2(f2tf(p0), f2tf(p1));
            *(uint2*)&Pw[g + 8][nt * 8 + 2 * tg] = make_uint2(f2tf(p2), f2tf(p3));
        }
        sum0 += __shfl_xor_sync(0xffffffffu, sum0, 1);
        sum0 += __shfl_xor_sync(0xffffffffu, sum0, 2);
        sum1 += __shfl_xor_sync(0xffffffffu, sum1, 1);
        sum1 += __shfl_xor_sync(0xffffffffu, sum1, 2);

        l0 = l0 * cr0 + sum0;
        l1 = l1 * cr1 + sum1;
        m0 = mn0;
        m1 = mn1;

        #pragma unroll
        for (int nt = 0; nt < 4; nt++) {
            o[nt][0] *= cr0; o[nt][1] *= cr0;
            o[nt][2] *= cr1; o[nt][3] *= cr1;
        }
        __syncwarp();

        // ---- O += P V ----
        #pragma unroll
        for (int ks = 0; ks < 8; ks++) {
            uint32_t a[4];
            a[0] = Pw[g    ][ks * 8 + tg];
            a[1] = Pw[g + 8][ks * 8 + tg];
            a[2] = Pw[g    ][ks * 8 + tg + 4];
            a[3] = Pw[g + 8][ks * 8 + tg + 4];
            #pragma unroll
            for (int nt = 0; nt < 4; nt++) {
                mma_tf32(o[nt], a, Vt[nt * 8 + g][ks * 8 + tg],
                                   Vt[nt * 8 + g][ks * 8 + tg + 4]);
            }
        }
        __syncthreads();
    }

    // ---- store unnormalized partials + (m, l) ----
    const int row0 = head * LTOK + qw + g;
    const int row1 = row0 + 8;
    float* pb0 = g_pacc + ((size_t)split * NROWS + row0) * HDIM + 2 * tg;
    float* pb1 = g_pacc + ((size_t)split * NROWS + row1) * HDIM + 2 * tg;
    #pragma unroll
    for (int nt = 0; nt < 4; nt++) {
        *(float2*)(pb0 + nt * 8) = make_float2(o[nt][0], o[nt][1]);
        *(float2*)(pb1 + nt * 8) = make_float2(o[nt][2], o[nt][3]);
    }
    if (tg == 0) {
        g_pm[split * NROWS + row0] = m0;
        g_pl[split * NROWS + row0] = l0;
        g_pm[split * NROWS + row1] = m1;
        g_pl[split * NROWS + row1] = l1;
    }
}

// ---------------------------------------------------------------------------------
// Merge split-K partials: o = sum_s e^{m_s-m*} acc_s / sum_s e^{m_s-m*} l_s
// One thread per (row, d4): 16384*8 threads.
// ---------------------------------------------------------------------------------
__global__ void __launch_bounds__(256) merge_kernel()
{
    const int idx = blockIdx.x * 256 + threadIdx.x;
    const int row = idx >> 3, d4 = idx & 7;

    float mv[SPLIT];
    float mstar = -INFINITY;
    #pragma unroll
    for (int s = 0; s < SPLIT; s++) {
        mv[s] = g_pm[s * NROWS + row];
        mstar = fmaxf(mstar, mv[s]);
    }
    float denom = 0.0f;
    float4 o = make_float4(0.f, 0.f, 0.f, 0.f);
    #pragma unroll
    for (int s = 0; s < SPLIT; s++) {
        const float w = __expf(mv[s] - mstar);
        denom = fmaf(w, g_pl[s * NROWS + row], denom);
        const float4 a = *(const float4*)(g_pacc + ((size_t)s * NROWS + row) * HDIM + d4 * 4);
        o.x = fmaf(w, a.x, o.x);
        o.y = fmaf(w, a.y, o.y);
        o.z = fmaf(w, a.z, o.z);
        o.w = fmaf(w, a.w, o.w);
    }
    const float inv = 1.0f / denom;
    o.x *= inv; o.y *= inv; o.z *= inv; o.w *= inv;

    const int head = row >> 11, q = row & (LTOK - 1);
    *(float4*)(g_att + (size_t)q * DMODEL + head * HDIM + d4 * 4) = o;
}

// ---------------------------------------------------------------------------------
// LayerNorm over last dim (256). One block per row.
// ---------------------------------------------------------------------------------
__global__ void __launch_bounds__(256) ln_kernel(
    const float* __restrict__ y, const float* __restrict__ g,
    const float* __restrict__ b, float* __restrict__ out)
{
    __shared__ float red[16];
    const int row = blockIdx.x, t = threadIdx.x;
    const float v = y[row * DMODEL + t];

    float s = v;
    #pragma unroll
    for (int o = 16; o; o >>= 1) s += __shfl_xor_sync(0xffffffffu, s, o);
    if ((t & 31) == 0) red[t >> 5] = s;
    __syncthreads();
    float tot = 0.f;
    #pragma unroll
    for (int w = 0; w < 8; w++) tot += red[w];
    const float mu = tot * (1.0f / 256.0f);

    const float d = v - mu;
    float sq = d * d;
    #pragma unroll
    for (int o = 16; o; o >>= 1) sq += __shfl_xor_sync(0xffffffffu, sq, o);
    if ((t & 31) == 0) red[8 + (t >> 5)] = sq;
    __syncthreads();
    float tot2 = 0.f;
    #pragma unroll
    for (int w = 0; w < 8; w++) tot2 += red[8 + w];
    const float var = tot2 * (1.0f / 256.0f);

    out[row * DMODEL + t] = d * rsqrtf(var + LN_EPS) * g[t] + b[t];
}

// ---------------------------------------------------------------------------------
extern "C" void kernel_launch(void* const* d_in, const int* in_sizes, int n_in,
                              void* d_out, int out_size)
{
    const float* x    = (const float*)d_in[0];
    const float* pts  = (const float*)d_in[1];
    const float* Wq   = (const float*)d_in[2];
    const float* bq   = (const float*)d_in[3];
    const float* Wk   = (const float*)d_in[4];
    const float* bk   = (const float*)d_in[5];
    const float* Wv   = (const float*)d_in[6];
    const float* bv   = (const float*)d_in[7];
    const float* Wo   = (const float*)d_in[8];
    const float* bo   = (const float*)d_in[9];
    const float* beta = (const float*)d_in[10];
    const float* kw1  = (const float*)d_in[11];
    const float* kb1  = (const float*)d_in[12];
    const float* kw2  = (const float*)d_in[13];
    const float* kb2  = (const float*)d_in[14];
    const float* lng  = (const float*)d_in[15];
    const float* lnb  = (const float*)d_in[16];
    float* out = (float*)d_out;

    float *Qb, *Kb, *Vb, *Ab, *Pb;
    cudaGetSymbolAddress((void**)&Qb, g_Q);
    cudaGetSymbolAddress((void**)&Kb, g_K);
    cudaGetSymbolAddress((void**)&Vb, g_V);
    cudaGetSymbolAddress((void**)&Ab, g_att);
    cudaGetSymbolAddress((void**)&Pb, g_proj);

    setup_geo_tables<<<1, 1>>>(kw1, kb1, kw2, kb2);

    gemm_qkv<<<dim3(DMODEL/64, LTOK/64, 3), 256>>>(x, Wq, bq, Wk, bk, Wv, bv, Qb, Kb, Vb);

    geo_bias_kernel<<<LTOK / 4, 256>>>(pts, beta);

    attn_kernel<<<NHEADS * 32 * SPLIT, 128>>>();
    merge_kernel<<<NROWS * 8 / 256, 256>>>();

    gemm_o<<<dim3(DMODEL/64, LTOK/64), 256>>>(Ab, Wo, bo, x, Pb);

    ln_kernel<<<LTOK, 256>>>(Pb, lng, lnb, out);
}

// round 7
// speedup vs baseline: 2.3270x; 1.1797x over previous
#include <cuda_runtime.h>
#include <math.h>
#include <stdint.h>

#define LTOK 2048
#define DMODEL 256
#define NHEADS 8
#define HDIM 32
#define SCALE 0.17677669529663687f  /* 32^-0.5 */
#define LN_EPS 1e-5f
#define SPLIT 4
#define KEYS_PER_SPLIT (LTOK / SPLIT)   /* 512 */
#define NROWS (NHEADS * LTOK)           /* 16384 */

// attn dynamic smem layout (uint32 words): Ks[64][36] | Vs[64][36] | Ps[4][32][68]
#define ATTN_KS_WORDS  (64 * 36)
#define ATTN_PS_OFF    (2 * ATTN_KS_WORDS)
#define ATTN_SMEM_BYTES ((ATTN_PS_OFF + 4 * 32 * 68) * 4)   /* 53248 */

// ---------------- scratch (device globals; no allocation allowed) ----------------
__device__ float g_Q[LTOK * DMODEL];
__device__ float g_K[LTOK * DMODEL];
__device__ float g_V[LTOK * DMODEL];
__device__ float g_bias[LTOK * LTOK];
__device__ float g_att[LTOK * DMODEL];
__device__ float g_proj[LTOK * DMODEL];
__device__ float g_pacc[SPLIT * NROWS * HDIM];
__device__ float g_pm[SPLIT * NROWS];
__device__ float g_pl[SPLIT * NROWS];
__device__ float g_T[32];
__device__ float g_S[33];
__device__ float g_C[33];

// ---------------------------------------------------------------------------------
// tf32 helpers
// ---------------------------------------------------------------------------------
__device__ __forceinline__ uint32_t f2tf(float x) {
    uint32_t u;
    asm("cvt.rna.tf32.f32 %0, %1;" : "=r"(u) : "f"(x));
    return u;
}

__device__ __forceinline__ void mma_tf32(float c[4], const uint32_t a[4],
                                         uint32_t b0, uint32_t b1) {
    asm volatile(
        "mma.sync.aligned.m16n8k8.row.col.f32.tf32.tf32.f32 "
        "{%0,%1,%2,%3}, {%4,%5,%6,%7}, {%8,%9}, {%0,%1,%2,%3};\n"
        : "+f"(c[0]), "+f"(c[1]), "+f"(c[2]), "+f"(c[3])
        : "r"(a[0]), "r"(a[1]), "r"(a[2]), "r"(a[3]), "r"(b0), "r"(b1));
}

// ---------------------------------------------------------------------------------
// tf32 mma GEMM: C[m][n] = sum_k A[m][k] * W[n][k] + bias[n] (+ resid)
// CTA: 128 threads / 4 warps; tile 64(M) x 64(N); k-chunks of 16.
// ---------------------------------------------------------------------------------
__device__ __forceinline__ void gemm_tf32_body(
    const float* __restrict__ A, const float* __restrict__ W,
    const float* __restrict__ bias, const float* __restrict__ resid,
    float* __restrict__ C,
    uint32_t As[64][20], uint32_t Ws[64][20])
{
    const int tid  = threadIdx.x;
    const int warp = tid >> 5;
    const int lane = tid & 31;
    const int g  = lane >> 2;
    const int tg = lane & 3;
    const int m0 = blockIdx.y * 64, n0 = blockIdx.x * 64;

    float acc[8][4];
    #pragma unroll
    for (int nt = 0; nt < 8; nt++)
        #pragma unroll
        for (int j = 0; j < 4; j++) acc[nt][j] = 0.0f;

    for (int k0 = 0; k0 < DMODEL; k0 += 16) {
        #pragma unroll
        for (int i = tid; i < 256; i += 128) {
            const int r = i >> 2, c4 = (i & 3) << 2;
            float4 av = *(const float4*)(A + (size_t)(m0 + r) * DMODEL + k0 + c4);
            *(uint4*)&As[r][c4] = make_uint4(f2tf(av.x), f2tf(av.y), f2tf(av.z), f2tf(av.w));
            float4 wv = *(const float4*)(W + (size_t)(n0 + r) * DMODEL + k0 + c4);
            *(uint4*)&Ws[r][c4] = make_uint4(f2tf(wv.x), f2tf(wv.y), f2tf(wv.z), f2tf(wv.w));
        }
        __syncthreads();

        #pragma unroll
        for (int kf = 0; kf < 2; kf++) {
            uint32_t a[4];
            a[0] = As[warp * 16 + g    ][kf * 8 + tg    ];
            a[1] = As[warp * 16 + g + 8][kf * 8 + tg    ];
            a[2] = As[warp * 16 + g    ][kf * 8 + tg + 4];
            a[3] = As[warp * 16 + g + 8][kf * 8 + tg + 4];
            #pragma unroll
            for (int nt = 0; nt < 8; nt++) {
                mma_tf32(acc[nt], a, Ws[nt * 8 + g][kf * 8 + tg],
                                     Ws[nt * 8 + g][kf * 8 + tg + 4]);
            }
        }
        __syncthreads();
    }

    const int mA = m0 + warp * 16 + g;
    const int mB = mA + 8;
    #pragma unroll
    for (int nt = 0; nt < 8; nt++) {
        const int n = n0 + nt * 8 + 2 * tg;
        float2 bb = *(const float2*)(bias + n);
        float2 vA = make_float2(acc[nt][0] + bb.x, acc[nt][1] + bb.y);
        float2 vB = make_float2(acc[nt][2] + bb.x, acc[nt][3] + bb.y);
        if (resid) {
            float2 rA = *(const float2*)(resid + (size_t)mA * DMODEL + n);
            float2 rB = *(const float2*)(resid + (size_t)mB * DMODEL + n);
            vA.x += rA.x; vA.y += rA.y;
            vB.x += rB.x; vB.y += rB.y;
        }
        *(float2*)(C + (size_t)mA * DMODEL + n) = vA;
        *(float2*)(C + (size_t)mB * DMODEL + n) = vB;
    }
}

__global__ void __launch_bounds__(128) gemm_qkv(
    const float* __restrict__ x,
    const float* __restrict__ Wq, const float* __restrict__ bq,
    const float* __restrict__ Wk, const float* __restrict__ bk,
    const float* __restrict__ Wv, const float* __restrict__ bv,
    float* __restrict__ Qo, float* __restrict__ Ko, float* __restrict__ Vo)
{
    __shared__ uint32_t As[64][20];
    __shared__ uint32_t Ws[64][20];
    const float* W; const float* b; float* C;
    if (blockIdx.z == 0)      { W = Wq; b = bq; C = Qo; }
    else if (blockIdx.z == 1) { W = Wk; b = bk; C = Ko; }
    else                      { W = Wv; b = bv; C = Vo; }
    gemm_tf32_body(x, W, b, nullptr, C, As, Ws);
}

__global__ void __launch_bounds__(128) gemm_o(
    const float* __restrict__ A, const float* __restrict__ W,
    const float* __restrict__ b, const float* __restrict__ resid,
    float* __restrict__ C)
{
    __shared__ uint32_t As[64][20];
    __shared__ uint32_t Ws[64][20];
    gemm_tf32_body(A, W, b, resid, C, As, Ws);
}

// ---------------------------------------------------------------------------------
// Setup: bias MLP piecewise-linear tables. 1 thread.
// ---------------------------------------------------------------------------------
__global__ void setup_geo_tables(
    const float* __restrict__ kw1, const float* __restrict__ kb1,
    const float* __restrict__ kw2, const float* __restrict__ kb2)
{
    float t[32], ds[32], dc[32];
    int n = 0;
    float S0 = 0.0f, C0 = kb2[0];
    for (int j = 0; j < 32; j++) {
        const float w1 = kw1[j], b1 = kb1[j], w2 = kw2[j];
        if (b1 > 0.0f) { S0 += w1 * w2; C0 += b1 * w2; }
        if (w1 > 0.0f && !(b1 > 0.0f)) {
            t[n] = -b1 / w1; ds[n] = w1 * w2; dc[n] = b1 * w2; n++;
        } else if (w1 < 0.0f && b1 > 0.0f) {
            t[n] = -b1 / w1; ds[n] = -w1 * w2; dc[n] = -b1 * w2; n++;
        }
    }
    for (int i = 1; i < n; i++) {
        float tv = t[i], sv = ds[i], cv = dc[i];
        int j = i - 1;
        while (j >= 0 && t[j] > tv) { t[j+1]=t[j]; ds[j+1]=ds[j]; dc[j+1]=dc[j]; j--; }
        t[j+1] = tv; ds[j+1] = sv; dc[j+1] = cv;
    }
    g_S[0] = S0; g_C[0] = C0;
    for (int i = 0; i < 32; i++) {
        if (i < n) {
            g_T[i] = t[i];
            g_S[i+1] = g_S[i] + ds[i];
            g_C[i+1] = g_C[i] + dc[i];
        } else {
            g_T[i] = INFINITY;
            g_S[i+1] = g_S[i];
            g_C[i+1] = g_C[i];
        }
    }
}

// ---------------------------------------------------------------------------------
// Geometric bias via table lookup.
// ---------------------------------------------------------------------------------
__global__ void __launch_bounds__(256) geo_bias_kernel(
    const float* __restrict__ pts, const float* __restrict__ beta)
{
    __shared__ float sp[LTOK * 3];
    __shared__ float sT[32], sS[33], sC[33];
    const int tid = threadIdx.x;
    for (int i = tid; i < LTOK * 3; i += 256) sp[i] = pts[i];
    if (tid < 32) sT[tid] = g_T[tid];
    if (tid < 33) { sS[tid] = g_S[tid]; sC[tid] = g_C[tid]; }
    __syncthreads();

    const float bet = beta[0];
    const int qbase = blockIdx.x * 4;

    #pragma unroll
    for (int qi = 0; qi < 4; qi++) {
        const int q = qbase + qi;
        const float qx = sp[q*3+0], qy = sp[q*3+1], qz = sp[q*3+2];
        for (int k = tid; k < LTOK; k += 256) {
            const float dx = qx - sp[k*3+0];
            const float dy = qy - sp[k*3+1];
            const float dz = qz - sp[k*3+2];
            const float d = sqrtf(dx*dx + dy*dy + dz*dz);
            int i = 0;
            #pragma unroll
            for (int s = 16; s; s >>= 1) if (sT[i + s - 1] < d) i += s;
            const float b = fmaf(sS[i], d, sC[i]);
            g_bias[q * LTOK + k] = bet * fminf(fmaxf(b, -10.0f), 0.0f);
        }
    }
}

// ---------------------------------------------------------------------------------
// tf32 mma flash attention, SPLIT-K x4, 32 queries per warp (2 row-tiles share
// every K/V fragment read). V stays row-major (B-fragment reads conflict-free).
// Dynamic smem: Ks[64][36] | Vs[64][36] | Ps[4][32][68] = 53,248 bytes.
// CTA: 128 threads / 4 warps / 128 queries; 512 keys per CTA.
// Grid = 8 heads * 16 qtiles * 4 splits = 512 CTAs.
// ---------------------------------------------------------------------------------
__global__ void __launch_bounds__(128) attn_kernel()
{
    extern __shared__ uint32_t sm[];
    uint32_t (*Ks)[36] = (uint32_t (*)[36])sm;                      // [64][36]
    uint32_t (*Vs)[36] = (uint32_t (*)[36])(sm + ATTN_KS_WORDS);    // [64][36]

    const int tid  = threadIdx.x;
    const int warp = tid >> 5;
    const int lane = tid & 31;
    const int g  = lane >> 2;
    const int tg = lane & 3;

    uint32_t (*Pw)[68] = (uint32_t (*)[68])(sm + ATTN_PS_OFF) + warp * 32; // [32][68]

    const int split = blockIdx.x & (SPLIT - 1);
    const int qtile = (blockIdx.x >> 2) & 15;
    const int head  = blockIdx.x >> 6;
    const int qw = qtile * 128 + warp * 32;
    const int kbeg = split * KEYS_PER_SPLIT;

    // Q fragments for two row-tiles (A = rows qw+0..15, B = rows qw+16..31)
    uint32_t qfA[4][4], qfB[4][4];
    {
        const float* Qb = g_Q + (size_t)qw * DMODEL + head * HDIM;
        #pragma unroll
        for (int ks = 0; ks < 4; ks++) {
            qfA[ks][0] = f2tf(SCALE * Qb[(g     ) * DMODEL + ks*8 + tg    ]);
            qfA[ks][1] = f2tf(SCALE * Qb[(g +  8) * DMODEL + ks*8 + tg    ]);
            qfA[ks][2] = f2tf(SCALE * Qb[(g     ) * DMODEL + ks*8 + tg + 4]);
            qfA[ks][3] = f2tf(SCALE * Qb[(g +  8) * DMODEL + ks*8 + tg + 4]);
            qfB[ks][0] = f2tf(SCALE * Qb[(g + 16) * DMODEL + ks*8 + tg    ]);
            qfB[ks][1] = f2tf(SCALE * Qb[(g + 24) * DMODEL + ks*8 + tg    ]);
            qfB[ks][2] = f2tf(SCALE * Qb[(g + 16) * DMODEL + ks*8 + tg + 4]);
            qfB[ks][3] = f2tf(SCALE * Qb[(g + 24) * DMODEL + ks*8 + tg + 4]);
        }
    }

    float oA[4][4], oB[4][4];
    #pragma unroll
    for (int nt = 0; nt < 4; nt++)
        #pragma unroll
        for (int j = 0; j < 4; j++) { oA[nt][j] = 0.0f; oB[nt][j] = 0.0f; }
    float mA0 = -INFINITY, mA1 = -INFINITY, mB0 = -INFINITY, mB1 = -INFINITY;
    float lA0 = 0.0f, lA1 = 0.0f, lB0 = 0.0f, lB1 = 0.0f;

    const float* b0p = g_bias + (size_t)(qw + g) * LTOK + 2 * tg;   // row A:g
    const float* b1p = b0p +  8 * LTOK;                              // row A:g+8
    const float* b2p = b0p + 16 * LTOK;                              // row B:g
    const float* b3p = b0p + 24 * LTOK;                              // row B:g+8

    #pragma unroll 1
    for (int t0 = kbeg; t0 < kbeg + KEYS_PER_SPLIT; t0 += 64) {
        // ---- stage K/V (both row-major, vectorized, conflict-free) ----
        #pragma unroll
        for (int i = tid; i < 512; i += 128) {
            const int r  = i >> 3;
            const int d4 = (i & 7) << 2;
            float4 kv = *(const float4*)(g_K + (size_t)(t0 + r) * DMODEL + head * HDIM + d4);
            *(uint4*)&Ks[r][d4] = make_uint4(f2tf(kv.x), f2tf(kv.y), f2tf(kv.z), f2tf(kv.w));
            float4 vv = *(const float4*)(g_V + (size_t)(t0 + r) * DMODEL + head * HDIM + d4);
            *(uint4*)&Vs[r][d4] = make_uint4(f2tf(vv.x), f2tf(vv.y), f2tf(vv.z), f2tf(vv.w));
        }
        __syncthreads();

        // ---- scores for both row-tiles; K fragments read once ----
        float sA[8][4], sB[8][4];
        #pragma unroll
        for (int nt = 0; nt < 8; nt++) {
            float2 bb0 = *(const float2*)(b0p + t0 + nt * 8);
            float2 bb1 = *(const float2*)(b1p + t0 + nt * 8);
            float2 bb2 = *(const float2*)(b2p + t0 + nt * 8);
            float2 bb3 = *(const float2*)(b3p + t0 + nt * 8);
            sA[nt][0] = bb0.x; sA[nt][1] = bb0.y;
            sA[nt][2] = bb1.x; sA[nt][3] = bb1.y;
            sB[nt][0] = bb2.x; sB[nt][1] = bb2.y;
            sB[nt][2] = bb3.x; sB[nt][3] = bb3.y;
            #pragma unroll
            for (int ks = 0; ks < 4; ks++) {
                const uint32_t kb0 = Ks[nt * 8 + g][ks * 8 + tg];
                const uint32_t kb1 = Ks[nt * 8 + g][ks * 8 + tg + 4];
                mma_tf32(sA[nt], qfA[ks], kb0, kb1);
                mma_tf32(sB[nt], qfB[ks], kb0, kb1);
            }
        }

        // ---- online softmax (4 row groups) ----
        float x0 = -INFINITY, x1 = -INFINITY, x2 = -INFINITY, x3 = -INFINITY;
        #pragma unroll
        for (int nt = 0; nt < 8; nt++) {
            x0 = fmaxf(x0, fmaxf(sA[nt][0], sA[nt][1]));
            x1 = fmaxf(x1, fmaxf(sA[nt][2], sA[nt][3]));
            x2 = fmaxf(x2, fmaxf(sB[nt][0], sB[nt][1]));
            x3 = fmaxf(x3, fmaxf(sB[nt][2], sB[nt][3]));
        }
        x0 = fmaxf(x0, __shfl_xor_sync(0xffffffffu, x0, 1));
        x0 = fmaxf(x0, __shfl_xor_sync(0xffffffffu, x0, 2));
        x1 = fmaxf(x1, __shfl_xor_sync(0xffffffffu, x1, 1));
        x1 = fmaxf(x1, __shfl_xor_sync(0xffffffffu, x1, 2));
        x2 = fmaxf(x2, __shfl_xor_sync(0xffffffffu, x2, 1));
        x2 = fmaxf(x2, __shfl_xor_sync(0xffffffffu, x2, 2));
        x3 = fmaxf(x3, __shfl_xor_sync(0xffffffffu, x3, 1));
        x3 = fmaxf(x3, __shfl_xor_sync(0xffffffffu, x3, 2));

        const float nA0 = fmaxf(mA0, x0), nA1 = fmaxf(mA1, x1);
        const float nB0 = fmaxf(mB0, x2), nB1 = fmaxf(mB1, x3);
        const float cA0 = __expf(mA0 - nA0), cA1 = __expf(mA1 - nA1);
        const float cB0 = __expf(mB0 - nB0), cB1 = __expf(mB1 - nB1);

        float uA0 = 0.f, uA1 = 0.f, uB0 = 0.f, uB1 = 0.f;
        #pragma unroll
        for (int nt = 0; nt < 8; nt++) {
            const float pA0 = __expf(sA[nt][0] - nA0);
            const float pA1 = __expf(sA[nt][1] - nA0);
            const float pA2 = __expf(sA[nt][2] - nA1);
            const float pA3 = __expf(sA[nt][3] - nA1);
            const float pB0 = __expf(sB[nt][0] - nB0);
            const float pB1 = __expf(sB[nt][1] - nB0);
            const float pB2 = __expf(sB[nt][2] - nB1);
            const float pB3 = __expf(sB[nt][3] - nB1);
            uA0 += pA0 + pA1; uA1 += pA2 + pA3;
            uB0 += pB0 + pB1; uB1 += pB2 + pB3;
            *(uint2*)&Pw[g     ][nt * 8 + 2 * tg] = make_uint2(f2tf(pA0), f2tf(pA1));
            *(uint2*)&Pw[g +  8][nt * 8 + 2 * tg] = make_uint2(f2tf(pA2), f2tf(pA3));
            *(uint2*)&Pw[g + 16][nt * 8 + 2 * tg] = make_uint2(f2tf(pB0), f2tf(pB1));
            *(uint2*)&Pw[g + 24][nt * 8 + 2 * tg] = make_uint2(f2tf(pB2), f2tf(pB3));
        }
        uA0 += __shfl_xor_sync(0xffffffffu, uA0, 1);
        uA0 += __shfl_xor_sync(0xffffffffu, uA0, 2);
        uA1 += __shfl_xor_sync(0xffffffffu, uA1, 1);
        uA1 += __shfl_xor_sync(0xffffffffu, uA1, 2);
        uB0 += __shfl_xor_sync(0xffffffffu, uB0, 1);
        uB0 += __shfl_xor_sync(0xffffffffu, uB0, 2);
        uB1 += __shfl_xor_sync(0xffffffffu, uB1, 1);
        uB1 += __shfl_xor_sync(0xffffffffu, uB1, 2);

        lA0 = lA0 * cA0 + uA0;  lA1 = lA1 * cA1 + uA1;
        lB0 = lB0 * cB0 + uB0;  lB1 = lB1 * cB1 + uB1;
        mA0 = nA0; mA1 = nA1; mB0 = nB0; mB1 = nB1;

        #pragma unroll
        for (int nt = 0; nt < 4; nt++) {
            oA[nt][0] *= cA0; oA[nt][1] *= cA0;
            oA[nt][2] *= cA1; oA[nt][3] *= cA1;
            oB[nt][0] *= cB0; oB[nt][1] *= cB0;
            oB[nt][2] *= cB1; oB[nt][3] *= cB1;
        }
        __syncwarp();

        // ---- O += P V : V fragments shared between both row-tiles ----
        #pragma unroll
        for (int ks = 0; ks < 8; ks++) {
            uint32_t aA[4], aB[4];
            aA[0] = Pw[g     ][ks * 8 + tg];
            aA[1] = Pw[g +  8][ks * 8 + tg];
            aA[2] = Pw[g     ][ks * 8 + tg + 4];
            aA[3] = Pw[g +  8][ks * 8 + tg + 4];
            aB[0] = Pw[g + 16][ks * 8 + tg];
            aB[1] = Pw[g + 24][ks * 8 + tg];
            aB[2] = Pw[g + 16][ks * 8 + tg + 4];
            aB[3] = Pw[g + 24][ks * 8 + tg + 4];
            #pragma unroll
            for (int nt = 0; nt < 4; nt++) {
                const uint32_t vb0 = Vs[ks * 8 + tg    ][nt * 8 + g];
                const uint32_t vb1 = Vs[ks * 8 + tg + 4][nt * 8 + g];
                mma_tf32(oA[nt], aA, vb0, vb1);
                mma_tf32(oB[nt], aB, vb0, vb1);
            }
        }
        __syncthreads();
    }

    // ---- store unnormalized partials + (m, l) ----
    const int rA0 = head * LTOK + qw + g;
    const int rA1 = rA0 + 8;
    const int rB0 = rA0 + 16;
    const int rB1 = rA0 + 24;
    float* pA0 = g_pacc + ((size_t)split * NROWS + rA0) * HDIM + 2 * tg;
    float* pA1 = g_pacc + ((size_t)split * NROWS + rA1) * HDIM + 2 * tg;
    float* pB0 = g_pacc + ((size_t)split * NROWS + rB0) * HDIM + 2 * tg;
    float* pB1 = g_pacc + ((size_t)split * NROWS + rB1) * HDIM + 2 * tg;
    #pragma unroll
    for (int nt = 0; nt < 4; nt++) {
        *(float2*)(pA0 + nt * 8) = make_float2(oA[nt][0], oA[nt][1]);
        *(float2*)(pA1 + nt * 8) = make_float2(oA[nt][2], oA[nt][3]);
        *(float2*)(pB0 + nt * 8) = make_float2(oB[nt][0], oB[nt][1]);
        *(float2*)(pB1 + nt * 8) = make_float2(oB[nt][2], oB[nt][3]);
    }
    if (tg == 0) {
        g_pm[split * NROWS + rA0] = mA0;  g_pl[split * NROWS + rA0] = lA0;
        g_pm[split * NROWS + rA1] = mA1;  g_pl[split * NROWS + rA1] = lA1;
        g_pm[split * NROWS + rB0] = mB0;  g_pl[split * NROWS + rB0] = lB0;
        g_pm[split * NROWS + rB1] = mB1;  g_pl[split * NROWS + rB1] = lB1;
    }
}

// ---------------------------------------------------------------------------------
// Merge split-K partials.
// ---------------------------------------------------------------------------------
__global__ void __launch_bounds__(256) merge_kernel()
{
    const int idx = blockIdx.x * 256 + threadIdx.x;
    const int row = idx >> 3, d4 = idx & 7;

    float mv[SPLIT];
    float mstar = -INFINITY;
    #pragma unroll
    for (int s = 0; s < SPLIT; s++) {
        mv[s] = g_pm[s * NROWS + row];
        mstar = fmaxf(mstar, mv[s]);
    }
    float denom = 0.0f;
    float4 o = make_float4(0.f, 0.f, 0.f, 0.f);
    #pragma unroll
    for (int s = 0; s < SPLIT; s++) {
        const float w = __expf(mv[s] - mstar);
        denom = fmaf(w, g_pl[s * NROWS + row], denom);
        const float4 a = *(const float4*)(g_pacc + ((size_t)s * NROWS + row) * HDIM + d4 * 4);
        o.x = fmaf(w, a.x, o.x);
        o.y = fmaf(w, a.y, o.y);
        o.z = fmaf(w, a.z, o.z);
        o.w = fmaf(w, a.w, o.w);
    }
    const float inv = 1.0f / denom;
    o.x *= inv; o.y *= inv; o.z *= inv; o.w *= inv;

    const int head = row >> 11, q = row & (LTOK - 1);
    *(float4*)(g_att + (size_t)q * DMODEL + head * HDIM + d4 * 4) = o;
}

// ---------------------------------------------------------------------------------
// LayerNorm over last dim (256). One block per row.
// ---------------------------------------------------------------------------------
__global__ void __launch_bounds__(256) ln_kernel(
    const float* __restrict__ y, const float* __restrict__ g,
    const float* __restrict__ b, float* __restrict__ out)
{
    __shared__ float red[16];
    const int row = blockIdx.x, t = threadIdx.x;
    const float v = y[row * DMODEL + t];

    float s = v;
    #pragma unroll
    for (int o = 16; o; o >>= 1) s += __shfl_xor_sync(0xffffffffu, s, o);
    if ((t & 31) == 0) red[t >> 5] = s;
    __syncthreads();
    float tot = 0.f;
    #pragma unroll
    for (int w = 0; w < 8; w++) tot += red[w];
    const float mu = tot * (1.0f / 256.0f);

    const float d = v - mu;
    float sq = d * d;
    #pragma unroll
    for (int o = 16; o; o >>= 1) sq += __shfl_xor_sync(0xffffffffu, sq, o);
    if ((t & 31) == 0) red[8 + (t >> 5)] = sq;
    __syncthreads();
    float tot2 = 0.f;
    #pragma unroll
    for (int w = 0; w < 8; w++) tot2 += red[8 + w];
    const float var = tot2 * (1.0f / 256.0f);

    out[row * DMODEL + t] = d * rsqrtf(var + LN_EPS) * g[t] + b[t];
}

// ---------------------------------------------------------------------------------
extern "C" void kernel_launch(void* const* d_in, const int* in_sizes, int n_in,
                              void* d_out, int out_size)
{
    const float* x    = (const float*)d_in[0];
    const float* pts  = (const float*)d_in[1];
    const float* Wq   = (const float*)d_in[2];
    const float* bq   = (const float*)d_in[3];
    const float* Wk   = (const float*)d_in[4];
    const float* bk   = (const float*)d_in[5];
    const float* Wv   = (const float*)d_in[6];
    const float* bv   = (const float*)d_in[7];
    const float* Wo   = (const float*)d_in[8];
    const float* bo   = (const float*)d_in[9];
    const float* beta = (const float*)d_in[10];
    const float* kw1  = (const float*)d_in[11];
    const float* kb1  = (const float*)d_in[12];
    const float* kw2  = (const float*)d_in[13];
    const float* kb2  = (const float*)d_in[14];
    const float* lng  = (const float*)d_in[15];
    const float* lnb  = (const float*)d_in[16];
    float* out = (float*)d_out;

    float *Qb, *Kb, *Vb, *Ab, *Pb;
    cudaGetSymbolAddress((void**)&Qb, g_Q);
    cudaGetSymbolAddress((void**)&Kb, g_K);
    cudaGetSymbolAddress((void**)&Vb, g_V);
    cudaGetSymbolAddress((void**)&Ab, g_att);
    cudaGetSymbolAddress((void**)&Pb, g_proj);

    // raise dynamic smem cap for attn (attribute set, not an allocation)
    cudaFuncSetAttribute(attn_kernel,
                         cudaFuncAttributeMaxDynamicSharedMemorySize,
                         ATTN_SMEM_BYTES);

    setup_geo_tables<<<1, 1>>>(kw1, kb1, kw2, kb2);

    gemm_qkv<<<dim3(DMODEL/64, LTOK/64, 3), 128>>>(x, Wq, bq, Wk, bk, Wv, bv, Qb, Kb, Vb);

    geo_bias_kernel<<<LTOK / 4, 256>>>(pts, beta);

    attn_kernel<<<NHEADS * 16 * SPLIT, 128, ATTN_SMEM_BYTES>>>();
    merge_kernel<<<NROWS * 8 / 256, 256>>>();

    gemm_o<<<dim3(DMODEL/64, LTOK/64), 128>>>(Ab, Wo, bo, x, Pb);

    ln_kernel<<<LTOK, 256>>>(Pb, lng, lnb, out);
}

// round 8
// speedup vs baseline: 2.6153x; 1.1239x over previous
#include <cuda_runtime.h>
#include <math.h>
#include <stdint.h>
#include <cuda_fp16.h>

#define LTOK 2048
#define DMODEL 256
#define NHEADS 8
#define HDIM 32
#define SCALE 0.17677669529663687f  /* 32^-0.5 */
#define LN_EPS 1e-5f
#define SPLIT 4
#define KEYS_PER_SPLIT (LTOK / SPLIT)   /* 512 */
#define NROWS (NHEADS * LTOK)           /* 16384 */

// ---------------- scratch (device globals; no allocation allowed) ----------------
__device__ float g_Q[LTOK * DMODEL];
__device__ float g_K[LTOK * DMODEL];
__device__ float g_V[LTOK * DMODEL];
__device__ float g_bias[LTOK * LTOK];
__device__ float g_att[LTOK * DMODEL];
__device__ float g_proj[LTOK * DMODEL];
__device__ float g_pacc[SPLIT * NROWS * HDIM];
__device__ float g_pm[SPLIT * NROWS];
__device__ float g_pl[SPLIT * NROWS];
__device__ float g_T[32];
__device__ float g_S[33];
__device__ float g_C[33];

// ---------------------------------------------------------------------------------
// mma helpers
// ---------------------------------------------------------------------------------
__device__ __forceinline__ uint32_t f2tf(float x) {
    uint32_t u;
    asm("cvt.rna.tf32.f32 %0, %1;" : "=r"(u) : "f"(x));
    return u;
}

// pack two f32 -> f16x2 (lo in low half)
__device__ __forceinline__ uint32_t pack_f16(float lo, float hi) {
    uint32_t r;
    asm("cvt.rn.f16x2.f32 %0, %1, %2;" : "=r"(r) : "f"(hi), "f"(lo));
    return r;
}

__device__ __forceinline__ void mma_tf32(float c[4], const uint32_t a[4],
                                         uint32_t b0, uint32_t b1) {
    asm volatile(
        "mma.sync.aligned.m16n8k8.row.col.f32.tf32.tf32.f32 "
        "{%0,%1,%2,%3}, {%4,%5,%6,%7}, {%8,%9}, {%0,%1,%2,%3};\n"
        : "+f"(c[0]), "+f"(c[1]), "+f"(c[2]), "+f"(c[3])
        : "r"(a[0]), "r"(a[1]), "r"(a[2]), "r"(a[3]), "r"(b0), "r"(b1));
}

__device__ __forceinline__ void mma_f16(float c[4], const uint32_t a[4],
                                        uint32_t b0, uint32_t b1) {
    asm volatile(
        "mma.sync.aligned.m16n8k16.row.col.f32.f16.f16.f32 "
        "{%0,%1,%2,%3}, {%4,%5,%6,%7}, {%8,%9}, {%0,%1,%2,%3};\n"
        : "+f"(c[0]), "+f"(c[1]), "+f"(c[2]), "+f"(c[3])
        : "r"(a[0]), "r"(a[1]), "r"(a[2]), "r"(a[3]), "r"(b0), "r"(b1));
}

// ---------------------------------------------------------------------------------
// tf32 mma GEMM: C[m][n] = sum_k A[m][k] * W[n][k] + bias[n] (+ resid)
// CTA: 128 threads / 4 warps; tile 64(M) x 64(N); k-chunks of 16.
// ---------------------------------------------------------------------------------
__device__ __forceinline__ void gemm_tf32_body(
    const float* __restrict__ A, const float* __restrict__ W,
    const float* __restrict__ bias, const float* __restrict__ resid,
    float* __restrict__ C,
    uint32_t As[64][20], uint32_t Ws[64][20])
{
    const int tid  = threadIdx.x;
    const int warp = tid >> 5;
    const int lane = tid & 31;
    const int g  = lane >> 2;
    const int tg = lane & 3;
    const int m0 = blockIdx.y * 64, n0 = blockIdx.x * 64;

    float acc[8][4];
    #pragma unroll
    for (int nt = 0; nt < 8; nt++)
        #pragma unroll
        for (int j = 0; j < 4; j++) acc[nt][j] = 0.0f;

    for (int k0 = 0; k0 < DMODEL; k0 += 16) {
        #pragma unroll
        for (int i = tid; i < 256; i += 128) {
            const int r = i >> 2, c4 = (i & 3) << 2;
            float4 av = *(const float4*)(A + (size_t)(m0 + r) * DMODEL + k0 + c4);
            *(uint4*)&As[r][c4] = make_uint4(f2tf(av.x), f2tf(av.y), f2tf(av.z), f2tf(av.w));
            float4 wv = *(const float4*)(W + (size_t)(n0 + r) * DMODEL + k0 + c4);
            *(uint4*)&Ws[r][c4] = make_uint4(f2tf(wv.x), f2tf(wv.y), f2tf(wv.z), f2tf(wv.w));
        }
        __syncthreads();

        #pragma unroll
        for (int kf = 0; kf < 2; kf++) {
            uint32_t a[4];
            a[0] = As[warp * 16 + g    ][kf * 8 + tg    ];
            a[1] = As[warp * 16 + g + 8][kf * 8 + tg    ];
            a[2] = As[warp * 16 + g    ][kf * 8 + tg + 4];
            a[3] = As[warp * 16 + g + 8][kf * 8 + tg + 4];
            #pragma unroll
            for (int nt = 0; nt < 8; nt++) {
                mma_tf32(acc[nt], a, Ws[nt * 8 + g][kf * 8 + tg],
                                     Ws[nt * 8 + g][kf * 8 + tg + 4]);
            }
        }
        __syncthreads();
    }

    const int mA = m0 + warp * 16 + g;
    const int mB = mA + 8;
    #pragma unroll
    for (int nt = 0; nt < 8; nt++) {
        const int n = n0 + nt * 8 + 2 * tg;
        float2 bb = *(const float2*)(bias + n);
        float2 vA = make_float2(acc[nt][0] + bb.x, acc[nt][1] + bb.y);
        float2 vB = make_float2(acc[nt][2] + bb.x, acc[nt][3] + bb.y);
        if (resid) {
            float2 rA = *(const float2*)(resid + (size_t)mA * DMODEL + n);
            float2 rB = *(const float2*)(resid + (size_t)mB * DMODEL + n);
            vA.x += rA.x; vA.y += rA.y;
            vB.x += rB.x; vB.y += rB.y;
        }
        *(float2*)(C + (size_t)mA * DMODEL + n) = vA;
        *(float2*)(C + (size_t)mB * DMODEL + n) = vB;
    }
}

__global__ void __launch_bounds__(128) gemm_qkv(
    const float* __restrict__ x,
    const float* __restrict__ Wq, const float* __restrict__ bq,
    const float* __restrict__ Wk, const float* __restrict__ bk,
    const float* __restrict__ Wv, const float* __restrict__ bv,
    float* __restrict__ Qo, float* __restrict__ Ko, float* __restrict__ Vo)
{
    __shared__ uint32_t As[64][20];
    __shared__ uint32_t Ws[64][20];
    const float* W; const float* b; float* C;
    if (blockIdx.z == 0)      { W = Wq; b = bq; C = Qo; }
    else if (blockIdx.z == 1) { W = Wk; b = bk; C = Ko; }
    else                      { W = Wv; b = bv; C = Vo; }
    gemm_tf32_body(x, W, b, nullptr, C, As, Ws);
}

__global__ void __launch_bounds__(128) gemm_o(
    const float* __restrict__ A, const float* __restrict__ W,
    const float* __restrict__ b, const float* __restrict__ resid,
    float* __restrict__ C)
{
    __shared__ uint32_t As[64][20];
    __shared__ uint32_t Ws[64][20];
    gemm_tf32_body(A, W, b, resid, C, As, Ws);
}

// ---------------------------------------------------------------------------------
// Setup: bias MLP piecewise-linear tables. 1 thread.
// ---------------------------------------------------------------------------------
__global__ void setup_geo_tables(
    const float* __restrict__ kw1, const float* __restrict__ kb1,
    const float* __restrict__ kw2, const float* __restrict__ kb2)
{
    float t[32], ds[32], dc[32];
    int n = 0;
    float S0 = 0.0f, C0 = kb2[0];
    for (int j = 0; j < 32; j++) {
        const float w1 = kw1[j], b1 = kb1[j], w2 = kw2[j];
        if (b1 > 0.0f) { S0 += w1 * w2; C0 += b1 * w2; }
        if (w1 > 0.0f && !(b1 > 0.0f)) {
            t[n] = -b1 / w1; ds[n] = w1 * w2; dc[n] = b1 * w2; n++;
        } else if (w1 < 0.0f && b1 > 0.0f) {
            t[n] = -b1 / w1; ds[n] = -w1 * w2; dc[n] = -b1 * w2; n++;
        }
    }
    for (int i = 1; i < n; i++) {
        float tv = t[i], sv = ds[i], cv = dc[i];
        int j = i - 1;
        while (j >= 0 && t[j] > tv) { t[j+1]=t[j]; ds[j+1]=ds[j]; dc[j+1]=dc[j]; j--; }
        t[j+1] = tv; ds[j+1] = sv; dc[j+1] = cv;
    }
    g_S[0] = S0; g_C[0] = C0;
    for (int i = 0; i < 32; i++) {
        if (i < n) {
            g_T[i] = t[i];
            g_S[i+1] = g_S[i] + ds[i];
            g_C[i+1] = g_C[i] + dc[i];
        } else {
            g_T[i] = INFINITY;
            g_S[i+1] = g_S[i];
            g_C[i+1] = g_C[i];
        }
    }
}

// ---------------------------------------------------------------------------------
// Geometric bias via table lookup.
// ---------------------------------------------------------------------------------
__global__ void __launch_bounds__(256) geo_bias_kernel(
    const float* __restrict__ pts, const float* __restrict__ beta)
{
    __shared__ float sp[LTOK * 3];
    __shared__ float sT[32], sS[33], sC[33];
    const int tid = threadIdx.x;
    for (int i = tid; i < LTOK * 3; i += 256) sp[i] = pts[i];
    if (tid < 32) sT[tid] = g_T[tid];
    if (tid < 33) { sS[tid] = g_S[tid]; sC[tid] = g_C[tid]; }
    __syncthreads();

    const float bet = beta[0];
    const int qbase = blockIdx.x * 4;

    #pragma unroll
    for (int qi = 0; qi < 4; qi++) {
        const int q = qbase + qi;
        const float qx = sp[q*3+0], qy = sp[q*3+1], qz = sp[q*3+2];
        for (int k = tid; k < LTOK; k += 256) {
            const float dx = qx - sp[k*3+0];
            const float dy = qy - sp[k*3+1];
            const float dz = qz - sp[k*3+2];
            const float d = sqrtf(dx*dx + dy*dy + dz*dz);
            int i = 0;
            #pragma unroll
            for (int s = 16; s; s >>= 1) if (sT[i + s - 1] < d) i += s;
            const float b = fmaf(sS[i], d, sC[i]);
            g_bias[q * LTOK + k] = bet * fminf(fmaxf(b, -10.0f), 0.0f);
        }
    }
}

// ---------------------------------------------------------------------------------
// Flash attention: tf32 mma scores + fp16 mma PV with REGISTER-DIRECT P
// (f16 score-C fragment layout == PV A fragment layout; no P smem round-trip).
// V transposed to f16 Vt[32 d][72-stride keys]; b-fragment LDS conflict-free.
// SPLIT-K x4; CTA: 128 threads / 4 warps / 128 queries; 512 keys per CTA.
// Grid = 8 heads * 16 qtiles * 4 splits = 512 CTAs.  Smem: 13.8 KB static.
// ---------------------------------------------------------------------------------
__global__ void __launch_bounds__(128) attn_kernel()
{
    __shared__ uint32_t Ks[64][36];   // K tile [key][d], tf32 bits
    __shared__ __half   Vt[32][72];   // V tile transposed [d][key], f16

    const int tid  = threadIdx.x;
    const int warp = tid >> 5;
    const int lane = tid & 31;
    const int g  = lane >> 2;
    const int tg = lane & 3;

    const int split = blockIdx.x & (SPLIT - 1);
    const int qtile = (blockIdx.x >> 2) & 15;
    const int head  = blockIdx.x >> 6;
    const int qw = qtile * 128 + warp * 32;
    const int kbeg = split * KEYS_PER_SPLIT;

    // Q fragments for two row-tiles (A = rows qw+0..15, B = rows qw+16..31)
    uint32_t qfA[4][4], qfB[4][4];
    {
        const float* Qb = g_Q + (size_t)qw * DMODEL + head * HDIM;
        #pragma unroll
        for (int ks = 0; ks < 4; ks++) {
            qfA[ks][0] = f2tf(SCALE * Qb[(g     ) * DMODEL + ks*8 + tg    ]);
            qfA[ks][1] = f2tf(SCALE * Qb[(g +  8) * DMODEL + ks*8 + tg    ]);
            qfA[ks][2] = f2tf(SCALE * Qb[(g     ) * DMODEL + ks*8 + tg + 4]);
            qfA[ks][3] = f2tf(SCALE * Qb[(g +  8) * DMODEL + ks*8 + tg + 4]);
            qfB[ks][0] = f2tf(SCALE * Qb[(g + 16) * DMODEL + ks*8 + tg    ]);
            qfB[ks][1] = f2tf(SCALE * Qb[(g + 24) * DMODEL + ks*8 + tg    ]);
            qfB[ks][2] = f2tf(SCALE * Qb[(g + 16) * DMODEL + ks*8 + tg + 4]);
            qfB[ks][3] = f2tf(SCALE * Qb[(g + 24) * DMODEL + ks*8 + tg + 4]);
        }
    }

    float oA[4][4], oB[4][4];
    #pragma unroll
    for (int nt = 0; nt < 4; nt++)
        #pragma unroll
        for (int j = 0; j < 4; j++) { oA[nt][j] = 0.0f; oB[nt][j] = 0.0f; }
    float mA0 = -INFINITY, mA1 = -INFINITY, mB0 = -INFINITY, mB1 = -INFINITY;
    float lA0 = 0.0f, lA1 = 0.0f, lB0 = 0.0f, lB1 = 0.0f;  // per-thread partial sums

    const float* b0p = g_bias + (size_t)(qw + g) * LTOK + 2 * tg;
    const float* b1p = b0p +  8 * LTOK;
    const float* b2p = b0p + 16 * LTOK;
    const float* b3p = b0p + 24 * LTOK;

    #pragma unroll 1
    for (int t0 = kbeg; t0 < kbeg + KEYS_PER_SPLIT; t0 += 64) {
        // ---- stage K (row-major tf32) ----
        #pragma unroll
        for (int i = tid; i < 512; i += 128) {
            const int r  = i >> 3;
            const int d4 = (i & 7) << 2;
            float4 kv = *(const float4*)(g_K + (size_t)(t0 + r) * DMODEL + head * HDIM + d4);
            *(uint4*)&Ks[r][d4] = make_uint4(f2tf(kv.x), f2tf(kv.y), f2tf(kv.z), f2tf(kv.w));
        }
        // ---- stage V transposed as f16 (key pairs packed) ----
        #pragma unroll
        for (int i = tid; i < 512; i += 128) {
            const int d  = i & 31;
            const int r4 = (i >> 5) << 2;
            const float* vp = g_V + (size_t)(t0 + r4) * DMODEL + head * HDIM + d;
            const float v0 = vp[0];
            const float v1 = vp[DMODEL];
            const float v2 = vp[2 * DMODEL];
            const float v3 = vp[3 * DMODEL];
            *(uint32_t*)&Vt[d][r4    ] = pack_f16(v0, v1);
            *(uint32_t*)&Vt[d][r4 + 2] = pack_f16(v2, v3);
        }
        __syncthreads();

        // ---- scores for both row-tiles (tf32); K fragments read once ----
        float sA[8][4], sB[8][4];
        #pragma unroll
        for (int nt = 0; nt < 8; nt++) {
            float2 bb0 = *(const float2*)(b0p + t0 + nt * 8);
            float2 bb1 = *(const float2*)(b1p + t0 + nt * 8);
            float2 bb2 = *(const float2*)(b2p + t0 + nt * 8);
            float2 bb3 = *(const float2*)(b3p + t0 + nt * 8);
            sA[nt][0] = bb0.x; sA[nt][1] = bb0.y;
            sA[nt][2] = bb1.x; sA[nt][3] = bb1.y;
            sB[nt][0] = bb2.x; sB[nt][1] = bb2.y;
            sB[nt][2] = bb3.x; sB[nt][3] = bb3.y;
            #pragma unroll
            for (int ks = 0; ks < 4; ks++) {
                const uint32_t kb0 = Ks[nt * 8 + g][ks * 8 + tg];
                const uint32_t kb1 = Ks[nt * 8 + g][ks * 8 + tg + 4];
                mma_tf32(sA[nt], qfA[ks], kb0, kb1);
                mma_tf32(sB[nt], qfB[ks], kb0, kb1);
            }
        }

        // ---- online softmax (4 row groups; quad shfl for row max) ----
        float x0 = -INFINITY, x1 = -INFINITY, x2 = -INFINITY, x3 = -INFINITY;
        #pragma unroll
        for (int nt = 0; nt < 8; nt++) {
            x0 = fmaxf(x0, fmaxf(sA[nt][0], sA[nt][1]));
            x1 = fmaxf(x1, fmaxf(sA[nt][2], sA[nt][3]));
            x2 = fmaxf(x2, fmaxf(sB[nt][0], sB[nt][1]));
            x3 = fmaxf(x3, fmaxf(sB[nt][2], sB[nt][3]));
        }
        x0 = fmaxf(x0, __shfl_xor_sync(0xffffffffu, x0, 1));
        x0 = fmaxf(x0, __shfl_xor_sync(0xffffffffu, x0, 2));
        x1 = fmaxf(x1, __shfl_xor_sync(0xffffffffu, x1, 1));
        x1 = fmaxf(x1, __shfl_xor_sync(0xffffffffu, x1, 2));
        x2 = fmaxf(x2, __shfl_xor_sync(0xffffffffu, x2, 1));
        x2 = fmaxf(x2, __shfl_xor_sync(0xffffffffu, x2, 2));
        x3 = fmaxf(x3, __shfl_xor_sync(0xffffffffu, x3, 1));
        x3 = fmaxf(x3, __shfl_xor_sync(0xffffffffu, x3, 2));

        const float nA0 = fmaxf(mA0, x0), nA1 = fmaxf(mA1, x1);
        const float nB0 = fmaxf(mB0, x2), nB1 = fmaxf(mB1, x3);
        const float cA0 = __expf(mA0 - nA0), cA1 = __expf(mA1 - nA1);
        const float cB0 = __expf(mB0 - nB0), cB1 = __expf(mB1 - nB1);

        // exps -> packed f16 P fragments (register-direct; zero smem traffic)
        uint32_t paL[8], paH[8], pbL[8], pbH[8];
        float uA0 = 0.f, uA1 = 0.f, uB0 = 0.f, uB1 = 0.f;
        #pragma unroll
        for (int nt = 0; nt < 8; nt++) {
            const float pA0 = __expf(sA[nt][0] - nA0);
            const float pA1 = __expf(sA[nt][1] - nA0);
            const float pA2 = __expf(sA[nt][2] - nA1);
            const float pA3 = __expf(sA[nt][3] - nA1);
            const float pB0 = __expf(sB[nt][0] - nB0);
            const float pB1 = __expf(sB[nt][1] - nB0);
            const float pB2 = __expf(sB[nt][2] - nB1);
            const float pB3 = __expf(sB[nt][3] - nB1);
            uA0 += pA0 + pA1; uA1 += pA2 + pA3;
            uB0 += pB0 + pB1; uB1 += pB2 + pB3;
            paL[nt] = pack_f16(pA0, pA1);
            paH[nt] = pack_f16(pA2, pA3);
            pbL[nt] = pack_f16(pB0, pB1);
            pbH[nt] = pack_f16(pB2, pB3);
        }
        // per-thread partial l (quad reduction deferred to the very end)
        lA0 = lA0 * cA0 + uA0;  lA1 = lA1 * cA1 + uA1;
        lB0 = lB0 * cB0 + uB0;  lB1 = lB1 * cB1 + uB1;
        mA0 = nA0; mA1 = nA1; mB0 = nB0; mB1 = nB1;

        #pragma unroll
        for (int nt = 0; nt < 4; nt++) {
            oA[nt][0] *= cA0; oA[nt][1] *= cA0;
            oA[nt][2] *= cA1; oA[nt][3] *= cA1;
            oB[nt][0] *= cB0; oB[nt][1] *= cB0;
            oB[nt][2] *= cB1; oB[nt][3] *= cB1;
        }

        // ---- O += P V : fp16 m16n8k16, P direct from registers ----
        #pragma unroll
        for (int kc = 0; kc < 4; kc++) {
            uint32_t aA[4], aB[4];
            aA[0] = paL[2*kc];   aA[1] = paH[2*kc];
            aA[2] = paL[2*kc+1]; aA[3] = paH[2*kc+1];
            aB[0] = pbL[2*kc];   aB[1] = pbH[2*kc];
            aB[2] = pbL[2*kc+1]; aB[3] = pbH[2*kc+1];
            #pragma unroll
            for (int nt = 0; nt < 4; nt++) {
                const uint32_t vb0 = *(const uint32_t*)&Vt[nt * 8 + g][kc * 16 + 2 * tg];
                const uint32_t vb1 = *(const uint32_t*)&Vt[nt * 8 + g][kc * 16 + 2 * tg + 8];
                mma_f16(oA[nt], aA, vb0, vb1);
                mma_f16(oB[nt], aB, vb0, vb1);
            }
        }
        __syncthreads();
    }

    // ---- final quad reduction of l ----
    lA0 += __shfl_xor_sync(0xffffffffu, lA0, 1);
    lA0 += __shfl_xor_sync(0xffffffffu, lA0, 2);
    lA1 += __shfl_xor_sync(0xffffffffu, lA1, 1);
    lA1 += __shfl_xor_sync(0xffffffffu, lA1, 2);
    lB0 += __shfl_xor_sync(0xffffffffu, lB0, 1);
    lB0 += __shfl_xor_sync(0xffffffffu, lB0, 2);
    lB1 += __shfl_xor_sync(0xffffffffu, lB1, 1);
    lB1 += __shfl_xor_sync(0xffffffffu, lB1, 2);

    // ---- store unnormalized partials + (m, l) ----
    const int rA0 = head * LTOK + qw + g;
    const int rA1 = rA0 + 8;
    const int rB0 = rA0 + 16;
    const int rB1 = rA0 + 24;
    float* pA0 = g_pacc + ((size_t)split * NROWS + rA0) * HDIM + 2 * tg;
    float* pA1 = g_pacc + ((size_t)split * NROWS + rA1) * HDIM + 2 * tg;
    float* pB0 = g_pacc + ((size_t)split * NROWS + rB0) * HDIM + 2 * tg;
    float* pB1 = g_pacc + ((size_t)split * NROWS + rB1) * HDIM + 2 * tg;
    #pragma unroll
    for (int nt = 0; nt < 4; nt++) {
        *(float2*)(pA0 + nt * 8) = make_float2(oA[nt][0], oA[nt][1]);
        *(float2*)(pA1 + nt * 8) = make_float2(oA[nt][2], oA[nt][3]);
        *(float2*)(pB0 + nt * 8) = make_float2(oB[nt][0], oB[nt][1]);
        *(float2*)(pB1 + nt * 8) = make_float2(oB[nt][2], oB[nt][3]);
    }
    if (tg == 0) {
        g_pm[split * NROWS + rA0] = mA0;  g_pl[split * NROWS + rA0] = lA0;
        g_pm[split * NROWS + rA1] = mA1;  g_pl[split * NROWS + rA1] = lA1;
        g_pm[split * NROWS + rB0] = mB0;  g_pl[split * NROWS + rB0] = lB0;
        g_pm[split * NROWS + rB1] = mB1;  g_pl[split * NROWS + rB1] = lB1;
    }
}

// ---------------------------------------------------------------------------------
// Merge split-K partials.
// ---------------------------------------------------------------------------------
__global__ void __launch_bounds__(256) merge_kernel()
{
    const int idx = blockIdx.x * 256 + threadIdx.x;
    const int row = idx >> 3, d4 = idx & 7;

    float mv[SPLIT];
    float mstar = -INFINITY;
    #pragma unroll
    for (int s = 0; s < SPLIT; s++) {
        mv[s] = g_pm[s * NROWS + row];
        mstar = fmaxf(mstar, mv[s]);
    }
    float denom = 0.0f;
    float4 o = make_float4(0.f, 0.f, 0.f, 0.f);
    #pragma unroll
    for (int s = 0; s < SPLIT; s++) {
        const float w = __expf(mv[s] - mstar);
        denom = fmaf(w, g_pl[s * NROWS + row], denom);
        const float4 a = *(const float4*)(g_pacc + ((size_t)s * NROWS + row) * HDIM + d4 * 4);
        o.x = fmaf(w, a.x, o.x);
        o.y = fmaf(w, a.y, o.y);
        o.z = fmaf(w, a.z, o.z);
        o.w = fmaf(w, a.w, o.w);
    }
    const float inv = 1.0f / denom;
    o.x *= inv; o.y *= inv; o.z *= inv; o.w *= inv;

    const int head = row >> 11, q = row & (LTOK - 1);
    *(float4*)(g_att + (size_t)q * DMODEL + head * HDIM + d4 * 4) = o;
}

// ---------------------------------------------------------------------------------
// LayerNorm over last dim (256). One block per row.
// ---------------------------------------------------------------------------------
__global__ void __launch_bounds__(256) ln_kernel(
    const float* __restrict__ y, const float* __restrict__ g,
    const float* __restrict__ b, float* __restrict__ out)
{
    __shared__ float red[16];
    const int row = blockIdx.x, t = threadIdx.x;
    const float v = y[row * DMODEL + t];

    float s = v;
    #pragma unroll
    for (int o = 16; o; o >>= 1) s += __shfl_xor_sync(0xffffffffu, s, o);
    if ((t & 31) == 0) red[t >> 5] = s;
    __syncthreads();
    float tot = 0.f;
    #pragma unroll
    for (int w = 0; w < 8; w++) tot += red[w];
    const float mu = tot * (1.0f / 256.0f);

    const float d = v - mu;
    float sq = d * d;
    #pragma unroll
    for (int o = 16; o; o >>= 1) sq += __shfl_xor_sync(0xffffffffu, sq, o);
    if ((t & 31) == 0) red[8 + (t >> 5)] = sq;
    __syncthreads();
    float tot2 = 0.f;
    #pragma unroll
    for (int w = 0; w < 8; w++) tot2 += red[8 + w];
    const float var = tot2 * (1.0f / 256.0f);

    out[row * DMODEL + t] = d * rsqrtf(var + LN_EPS) * g[t] + b[t];
}

// ---------------------------------------------------------------------------------
extern "C" void kernel_launch(void* const* d_in, const int* in_sizes, int n_in,
                              void* d_out, int out_size)
{
    const float* x    = (const float*)d_in[0];
    const float* pts  = (const float*)d_in[1];
    const float* Wq   = (const float*)d_in[2];
    const float* bq   = (const float*)d_in[3];
    const float* Wk   = (const float*)d_in[4];
    const float* bk   = (const float*)d_in[5];
    const float* Wv   = (const float*)d_in[6];
    const float* bv   = (const float*)d_in[7];
    const float* Wo   = (const float*)d_in[8];
    const float* bo   = (const float*)d_in[9];
    const float* beta = (const float*)d_in[10];
    const float* kw1  = (const float*)d_in[11];
    const float* kb1  = (const float*)d_in[12];
    const float* kw2  = (const float*)d_in[13];
    const float* kb2  = (const float*)d_in[14];
    const float* lng  = (const float*)d_in[15];
    const float* lnb  = (const float*)d_in[16];
    float* out = (float*)d_out;

    float *Qb, *Kb, *Vb, *Ab, *Pb;
    cudaGetSymbolAddress((void**)&Qb, g_Q);
    cudaGetSymbolAddress((void**)&Kb, g_K);
    cudaGetSymbolAddress((void**)&Vb, g_V);
    cudaGetSymbolAddress((void**)&Ab, g_att);
    cudaGetSymbolAddress((void**)&Pb, g_proj);

    setup_geo_tables<<<1, 1>>>(kw1, kb1, kw2, kb2);

    gemm_qkv<<<dim3(DMODEL/64, LTOK/64, 3), 128>>>(x, Wq, bq, Wk, bk, Wv, bv, Qb, Kb, Vb);

    geo_bias_kernel<<<LTOK / 4, 256>>>(pts, beta);

    attn_kernel<<<NHEADS * 16 * SPLIT, 128>>>();
    merge_kernel<<<NROWS * 8 / 256, 256>>>();

    gemm_o<<<dim3(DMODEL/64, LTOK/64), 128>>>(Ab, Wo, bo, x, Pb);

    ln_kernel<<<LTOK, 256>>>(Pb, lng, lnb, out);
}

// round 9
// speedup vs baseline: 2.8117x; 1.0751x over previous
#include <cuda_runtime.h>
#include <math.h>
#include <stdint.h>
#include <cuda_fp16.h>

#define LTOK 2048
#define DMODEL 256
#define NHEADS 8
#define HDIM 32
#define SCALE 0.17677669529663687f  /* 32^-0.5 */
#define LN_EPS 1e-5f
#define SPLIT 8
#define KEYS_PER_SPLIT (LTOK / SPLIT)   /* 256 */
#define NROWS (NHEADS * LTOK)           /* 16384 */

// ---------------- scratch (device globals; no allocation allowed) ----------------
__device__ float g_Q[LTOK * DMODEL];
__device__ float g_K[LTOK * DMODEL];
__device__ float g_V[LTOK * DMODEL];
__device__ float g_bias[LTOK * LTOK];
__device__ float g_att[LTOK * DMODEL];
__device__ float g_proj[LTOK * DMODEL];
__device__ float g_pacc[SPLIT * NROWS * HDIM];
__device__ float g_pm[SPLIT * NROWS];
__device__ float g_pl[SPLIT * NROWS];
__device__ float g_T[32];
__device__ float g_S[33];
__device__ float g_C[33];

// ---------------------------------------------------------------------------------
// mma helpers (tf32 operands passed as RAW f32 bits: HMMA.TF32 reads top 19 bits)
// ---------------------------------------------------------------------------------
__device__ __forceinline__ uint32_t pack_f16(float lo, float hi) {
    uint32_t r;
    asm("cvt.rn.f16x2.f32 %0, %1, %2;" : "=r"(r) : "f"(hi), "f"(lo));
    return r;
}

__device__ __forceinline__ void mma_tf32(float c[4], const uint32_t a[4],
                                         uint32_t b0, uint32_t b1) {
    asm volatile(
        "mma.sync.aligned.m16n8k8.row.col.f32.tf32.tf32.f32 "
        "{%0,%1,%2,%3}, {%4,%5,%6,%7}, {%8,%9}, {%0,%1,%2,%3};\n"
        : "+f"(c[0]), "+f"(c[1]), "+f"(c[2]), "+f"(c[3])
        : "r"(a[0]), "r"(a[1]), "r"(a[2]), "r"(a[3]), "r"(b0), "r"(b1));
}

__device__ __forceinline__ void mma_f16(float c[4], const uint32_t a[4],
                                        uint32_t b0, uint32_t b1) {
    asm volatile(
        "mma.sync.aligned.m16n8k16.row.col.f32.f16.f16.f32 "
        "{%0,%1,%2,%3}, {%4,%5,%6,%7}, {%8,%9}, {%0,%1,%2,%3};\n"
        : "+f"(c[0]), "+f"(c[1]), "+f"(c[2]), "+f"(c[3])
        : "r"(a[0]), "r"(a[1]), "r"(a[2]), "r"(a[3]), "r"(b0), "r"(b1));
}

// ---------------------------------------------------------------------------------
// tf32 mma GEMM: C[m][n] = sum_k A[m][k] * W[n][k] + bias[n] (+ resid)
// CTA: 128 threads / 4 warps; tile 64(M) x 64(N); k-chunks of 16. Raw-bit staging.
// ---------------------------------------------------------------------------------
__device__ __forceinline__ void gemm_tf32_body(
    const float* __restrict__ A, const float* __restrict__ W,
    const float* __restrict__ bias, const float* __restrict__ resid,
    float* __restrict__ C,
    uint32_t As[64][20], uint32_t Ws[64][20])
{
    const int tid  = threadIdx.x;
    const int warp = tid >> 5;
    const int lane = tid & 31;
    const int g  = lane >> 2;
    const int tg = lane & 3;
    const int m0 = blockIdx.y * 64, n0 = blockIdx.x * 64;

    float acc[8][4];
    #pragma unroll
    for (int nt = 0; nt < 8; nt++)
        #pragma unroll
        for (int j = 0; j < 4; j++) acc[nt][j] = 0.0f;

    for (int k0 = 0; k0 < DMODEL; k0 += 16) {
        #pragma unroll
        for (int i = tid; i < 256; i += 128) {
            const int r = i >> 2, c4 = (i & 3) << 2;
            *(uint4*)&As[r][c4] = *(const uint4*)(A + (size_t)(m0 + r) * DMODEL + k0 + c4);
            *(uint4*)&Ws[r][c4] = *(const uint4*)(W + (size_t)(n0 + r) * DMODEL + k0 + c4);
        }
        __syncthreads();

        #pragma unroll
        for (int kf = 0; kf < 2; kf++) {
            uint32_t a[4];
            a[0] = As[warp * 16 + g    ][kf * 8 + tg    ];
            a[1] = As[warp * 16 + g + 8][kf * 8 + tg    ];
            a[2] = As[warp * 16 + g    ][kf * 8 + tg + 4];
            a[3] = As[warp * 16 + g + 8][kf * 8 + tg + 4];
            #pragma unroll
            for (int nt = 0; nt < 8; nt++) {
                mma_tf32(acc[nt], a, Ws[nt * 8 + g][kf * 8 + tg],
                                     Ws[nt * 8 + g][kf * 8 + tg + 4]);
            }
        }
        __syncthreads();
    }

    const int mA = m0 + warp * 16 + g;
    const int mB = mA + 8;
    #pragma unroll
    for (int nt = 0; nt < 8; nt++) {
        const int n = n0 + nt * 8 + 2 * tg;
        float2 bb = *(const float2*)(bias + n);
        float2 vA = make_float2(acc[nt][0] + bb.x, acc[nt][1] + bb.y);
        float2 vB = make_float2(acc[nt][2] + bb.x, acc[nt][3] + bb.y);
        if (resid) {
            float2 rA = *(const float2*)(resid + (size_t)mA * DMODEL + n);
            float2 rB = *(const float2*)(resid + (size_t)mB * DMODEL + n);
            vA.x += rA.x; vA.y += rA.y;
            vB.x += rB.x; vB.y += rB.y;
        }
        *(float2*)(C + (size_t)mA * DMODEL + n) = vA;
        *(float2*)(C + (size_t)mB * DMODEL + n) = vB;
    }
}

__global__ void __launch_bounds__(128) gemm_qkv(
    const float* __restrict__ x,
    const float* __restrict__ Wq, const float* __restrict__ bq,
    const float* __restrict__ Wk, const float* __restrict__ bk,
    const float* __restrict__ Wv, const float* __restrict__ bv,
    float* __restrict__ Qo, float* __restrict__ Ko, float* __restrict__ Vo)
{
    __shared__ uint32_t As[64][20];
    __shared__ uint32_t Ws[64][20];
    const float* W; const float* b; float* C;
    if (blockIdx.z == 0)      { W = Wq; b = bq; C = Qo; }
    else if (blockIdx.z == 1) { W = Wk; b = bk; C = Ko; }
    else                      { W = Wv; b = bv; C = Vo; }
    gemm_tf32_body(x, W, b, nullptr, C, As, Ws);
}

__global__ void __launch_bounds__(128) gemm_o(
    const float* __restrict__ A, const float* __restrict__ W,
    const float* __restrict__ b, const float* __restrict__ resid,
    float* __restrict__ C)
{
    __shared__ uint32_t As[64][20];
    __shared__ uint32_t Ws[64][20];
    gemm_tf32_body(A, W, b, resid, C, As, Ws);
}

// ---------------------------------------------------------------------------------
// Setup: bias MLP piecewise-linear tables. 1 thread.
// ---------------------------------------------------------------------------------
__global__ void setup_geo_tables(
    const float* __restrict__ kw1, const float* __restrict__ kb1,
    const float* __restrict__ kw2, const float* __restrict__ kb2)
{
    float t[32], ds[32], dc[32];
    int n = 0;
    float S0 = 0.0f, C0 = kb2[0];
    for (int j = 0; j < 32; j++) {
        const float w1 = kw1[j], b1 = kb1[j], w2 = kw2[j];
        if (b1 > 0.0f) { S0 += w1 * w2; C0 += b1 * w2; }
        if (w1 > 0.0f && !(b1 > 0.0f)) {
            t[n] = -b1 / w1; ds[n] = w1 * w2; dc[n] = b1 * w2; n++;
        } else if (w1 < 0.0f && b1 > 0.0f) {
            t[n] = -b1 / w1; ds[n] = -w1 * w2; dc[n] = -b1 * w2; n++;
        }
    }
    for (int i = 1; i < n; i++) {
        float tv = t[i], sv = ds[i], cv = dc[i];
        int j = i - 1;
        while (j >= 0 && t[j] > tv) { t[j+1]=t[j]; ds[j+1]=ds[j]; dc[j+1]=dc[j]; j--; }
        t[j+1] = tv; ds[j+1] = sv; dc[j+1] = cv;
    }
    g_S[0] = S0; g_C[0] = C0;
    for (int i = 0; i < 32; i++) {
        if (i < n) {
            g_T[i] = t[i];
            g_S[i+1] = g_S[i] + ds[i];
            g_C[i+1] = g_C[i] + dc[i];
        } else {
            g_T[i] = INFINITY;
            g_S[i+1] = g_S[i];
            g_C[i+1] = g_C[i];
        }
    }
}

// ---------------------------------------------------------------------------------
// Geometric bias via table lookup.
// ---------------------------------------------------------------------------------
__global__ void __launch_bounds__(256) geo_bias_kernel(
    const float* __restrict__ pts, const float* __restrict__ beta)
{
    __shared__ float sp[LTOK * 3];
    __shared__ float sT[32], sS[33], sC[33];
    const int tid = threadIdx.x;
    for (int i = tid; i < LTOK * 3; i += 256) sp[i] = pts[i];
    if (tid < 32) sT[tid] = g_T[tid];
    if (tid < 33) { sS[tid] = g_S[tid]; sC[tid] = g_C[tid]; }
    __syncthreads();

    const float bet = beta[0];
    const int qbase = blockIdx.x * 4;

    #pragma unroll
    for (int qi = 0; qi < 4; qi++) {
        const int q = qbase + qi;
        const float qx = sp[q*3+0], qy = sp[q*3+1], qz = sp[q*3+2];
        for (int k = tid; k < LTOK; k += 256) {
            const float dx = qx - sp[k*3+0];
            const float dy = qy - sp[k*3+1];
            const float dz = qz - sp[k*3+2];
            const float d = sqrtf(dx*dx + dy*dy + dz*dz);
            int i = 0;
            #pragma unroll
            for (int s = 16; s; s >>= 1) if (sT[i + s - 1] < d) i += s;
            const float b = fmaf(sS[i], d, sC[i]);
            g_bias[q * LTOK + k] = bet * fminf(fmaxf(b, -10.0f), 0.0f);
        }
    }
}

// ---------------------------------------------------------------------------------
// Flash attention: tf32 mma scores (raw f32-bit operands) + fp16 mma PV with
// register-direct P. SPLIT-K x8 for wave-quantization efficiency.
// CTA: 128 threads / 4 warps / 128 queries; 256 keys per CTA (4 tiles of 64).
// Grid = 8 heads * 16 qtiles * 8 splits = 1024 CTAs. Smem: 13.8 KB static.
// Bias loads software-pipelined one nt-step ahead of the score mma chain.
// ---------------------------------------------------------------------------------
__global__ void __launch_bounds__(128) attn_kernel()
{
    __shared__ uint32_t Ks[64][36];   // K tile [key][d], raw f32 bits (tf32 mma)
    __shared__ __half   Vt[32][72];   // V tile transposed [d][key], f16

    const int tid  = threadIdx.x;
    const int warp = tid >> 5;
    const int lane = tid & 31;
    const int g  = lane >> 2;
    const int tg = lane & 3;

    const int split = blockIdx.x & (SPLIT - 1);
    const int qtile = (blockIdx.x >> 3) & 15;
    const int head  = blockIdx.x >> 7;
    const int qw = qtile * 128 + warp * 32;
    const int kbeg = split * KEYS_PER_SPLIT;

    // Q fragments for two row-tiles (raw bits, pre-scaled)
    uint32_t qfA[4][4], qfB[4][4];
    {
        const float* Qb = g_Q + (size_t)qw * DMODEL + head * HDIM;
        #pragma unroll
        for (int ks = 0; ks < 4; ks++) {
            qfA[ks][0] = __float_as_uint(SCALE * Qb[(g     ) * DMODEL + ks*8 + tg    ]);
            qfA[ks][1] = __float_as_uint(SCALE * Qb[(g +  8) * DMODEL + ks*8 + tg    ]);
            qfA[ks][2] = __float_as_uint(SCALE * Qb[(g     ) * DMODEL + ks*8 + tg + 4]);
            qfA[ks][3] = __float_as_uint(SCALE * Qb[(g +  8) * DMODEL + ks*8 + tg + 4]);
            qfB[ks][0] = __float_as_uint(SCALE * Qb[(g + 16) * DMODEL + ks*8 + tg    ]);
            qfB[ks][1] = __float_as_uint(SCALE * Qb[(g + 24) * DMODEL + ks*8 + tg    ]);
            qfB[ks][2] = __float_as_uint(SCALE * Qb[(g + 16) * DMODEL + ks*8 + tg + 4]);
            qfB[ks][3] = __float_as_uint(SCALE * Qb[(g + 24) * DMODEL + ks*8 + tg + 4]);
        }
    }

    float oA[4][4], oB[4][4];
    #pragma unroll
    for (int nt = 0; nt < 4; nt++)
        #pragma unroll
        for (int j = 0; j < 4; j++) { oA[nt][j] = 0.0f; oB[nt][j] = 0.0f; }
    float mA0 = -INFINITY, mA1 = -INFINITY, mB0 = -INFINITY, mB1 = -INFINITY;
    float lA0 = 0.0f, lA1 = 0.0f, lB0 = 0.0f, lB1 = 0.0f;

    const float* b0p = g_bias + (size_t)(qw + g) * LTOK + 2 * tg;
    const float* b1p = b0p +  8 * LTOK;
    const float* b2p = b0p + 16 * LTOK;
    const float* b3p = b0p + 24 * LTOK;

    #pragma unroll 1
    for (int t0 = kbeg; t0 < kbeg + KEYS_PER_SPLIT; t0 += 64) {
        // ---- stage K (raw f32 bits, pure copy) ----
        #pragma unroll
        for (int i = tid; i < 512; i += 128) {
            const int r  = i >> 3;
            const int d4 = (i & 7) << 2;
            *(uint4*)&Ks[r][d4] =
                *(const uint4*)(g_K + (size_t)(t0 + r) * DMODEL + head * HDIM + d4);
        }
        // ---- stage V transposed as f16 (key pairs packed) ----
        #pragma unroll
        for (int i = tid; i < 512; i += 128) {
            const int d  = i & 31;
            const int r4 = (i >> 5) << 2;
            const float* vp = g_V + (size_t)(t0 + r4) * DMODEL + head * HDIM + d;
            const float v0 = vp[0];
            const float v1 = vp[DMODEL];
            const float v2 = vp[2 * DMODEL];
            const float v3 = vp[3 * DMODEL];
            *(uint32_t*)&Vt[d][r4    ] = pack_f16(v0, v1);
            *(uint32_t*)&Vt[d][r4 + 2] = pack_f16(v2, v3);
        }
        __syncthreads();

        // ---- scores with bias pipelined one nt ahead of the mma chain ----
        float sA[8][4], sB[8][4];
        float2 nb0 = *(const float2*)(b0p + t0);
        float2 nb1 = *(const float2*)(b1p + t0);
        float2 nb2 = *(const float2*)(b2p + t0);
        float2 nb3 = *(const float2*)(b3p + t0);
        #pragma unroll
        for (int nt = 0; nt < 8; nt++) {
            const float2 bb0 = nb0, bb1 = nb1, bb2 = nb2, bb3 = nb3;
            if (nt < 7) {
                nb0 = *(const float2*)(b0p + t0 + (nt + 1) * 8);
                nb1 = *(const float2*)(b1p + t0 + (nt + 1) * 8);
                nb2 = *(const float2*)(b2p + t0 + (nt + 1) * 8);
                nb3 = *(const float2*)(b3p + t0 + (nt + 1) * 8);
            }
            sA[nt][0] = bb0.x; sA[nt][1] = bb0.y;
            sA[nt][2] = bb1.x; sA[nt][3] = bb1.y;
            sB[nt][0] = bb2.x; sB[nt][1] = bb2.y;
            sB[nt][2] = bb3.x; sB[nt][3] = bb3.y;
            #pragma unroll
            for (int ks = 0; ks < 4; ks++) {
                const uint32_t kb0 = Ks[nt * 8 + g][ks * 8 + tg];
                const uint32_t kb1 = Ks[nt * 8 + g][ks * 8 + tg + 4];
                mma_tf32(sA[nt], qfA[ks], kb0, kb1);
                mma_tf32(sB[nt], qfB[ks], kb0, kb1);
            }
        }

        // ---- online softmax (4 row groups; quad shfl for row max) ----
        float x0 = -INFINITY, x1 = -INFINITY, x2 = -INFINITY, x3 = -INFINITY;
        #pragma unroll
        for (int nt = 0; nt < 8; nt++) {
            x0 = fmaxf(x0, fmaxf(sA[nt][0], sA[nt][1]));
            x1 = fmaxf(x1, fmaxf(sA[nt][2], sA[nt][3]));
            x2 = fmaxf(x2, fmaxf(sB[nt][0], sB[nt][1]));
            x3 = fmaxf(x3, fmaxf(sB[nt][2], sB[nt][3]));
        }
        x0 = fmaxf(x0, __shfl_xor_sync(0xffffffffu, x0, 1));
        x0 = fmaxf(x0, __shfl_xor_sync(0xffffffffu, x0, 2));
        x1 = fmaxf(x1, __shfl_xor_sync(0xffffffffu, x1, 1));
        x1 = fmaxf(x1, __shfl_xor_sync(0xffffffffu, x1, 2));
        x2 = fmaxf(x2, __shfl_xor_sync(0xffffffffu, x2, 1));
        x2 = fmaxf(x2, __shfl_xor_sync(0xffffffffu, x2, 2));
        x3 = fmaxf(x3, __shfl_xor_sync(0xffffffffu, x3, 1));
        x3 = fmaxf(x3, __shfl_xor_sync(0xffffffffu, x3, 2));

        const float nA0 = fmaxf(mA0, x0), nA1 = fmaxf(mA1, x1);
        const float nB0 = fmaxf(mB0, x2), nB1 = fmaxf(mB1, x3);
        const float cA0 = __expf(mA0 - nA0), cA1 = __expf(mA1 - nA1);
        const float cB0 = __expf(mB0 - nB0), cB1 = __expf(mB1 - nB1);

        // exps -> packed f16 P fragments (register-direct)
        uint32_t paL[8], paH[8], pbL[8], pbH[8];
        float uA0 = 0.f, uA1 = 0.f, uB0 = 0.f, uB1 = 0.f;
        #pragma unroll
        for (int nt = 0; nt < 8; nt++) {
            const float pA0 = __expf(sA[nt][0] - nA0);
            const float pA1 = __expf(sA[nt][1] - nA0);
            const float pA2 = __expf(sA[nt][2] - nA1);
            const float pA3 = __expf(sA[nt][3] - nA1);
            const float pB0 = __expf(sB[nt][0] - nB0);
            const float pB1 = __expf(sB[nt][1] - nB0);
            const float pB2 = __expf(sB[nt][2] - nB1);
            const float pB3 = __expf(sB[nt][3] - nB1);
            uA0 += pA0 + pA1; uA1 += pA2 + pA3;
            uB0 += pB0 + pB1; uB1 += pB2 + pB3;
            paL[nt] = pack_f16(pA0, pA1);
            paH[nt] = pack_f16(pA2, pA3);
            pbL[nt] = pack_f16(pB0, pB1);
            pbH[nt] = pack_f16(pB2, pB3);
        }
        lA0 = lA0 * cA0 + uA0;  lA1 = lA1 * cA1 + uA1;
        lB0 = lB0 * cB0 + uB0;  lB1 = lB1 * cB1 + uB1;
        mA0 = nA0; mA1 = nA1; mB0 = nB0; mB1 = nB1;

        #pragma unroll
        for (int nt = 0; nt < 4; nt++) {
            oA[nt][0] *= cA0; oA[nt][1] *= cA0;
            oA[nt][2] *= cA1; oA[nt][3] *= cA1;
            oB[nt][0] *= cB0; oB[nt][1] *= cB0;
            oB[nt][2] *= cB1; oB[nt][3] *= cB1;
        }

        // ---- O += P V : fp16 m16n8k16, P direct from registers ----
        #pragma unroll
        for (int kc = 0; kc < 4; kc++) {
            uint32_t aA[4], aB[4];
            aA[0] = paL[2*kc];   aA[1] = paH[2*kc];
            aA[2] = paL[2*kc+1]; aA[3] = paH[2*kc+1];
            aB[0] = pbL[2*kc];   aB[1] = pbH[2*kc];
            aB[2] = pbL[2*kc+1]; aB[3] = pbH[2*kc+1];
            #pragma unroll
            for (int nt = 0; nt < 4; nt++) {
                const uint32_t vb0 = *(const uint32_t*)&Vt[nt * 8 + g][kc * 16 + 2 * tg];
                const uint32_t vb1 = *(const uint32_t*)&Vt[nt * 8 + g][kc * 16 + 2 * tg + 8];
                mma_f16(oA[nt], aA, vb0, vb1);
                mma_f16(oB[nt], aB, vb0, vb1);
            }
        }
        __syncthreads();
    }

    // ---- final quad reduction of l ----
    lA0 += __shfl_xor_sync(0xffffffffu, lA0, 1);
    lA0 += __shfl_xor_sync(0xffffffffu, lA0, 2);
    lA1 += __shfl_xor_sync(0xffffffffu, lA1, 1);
    lA1 += __shfl_xor_sync(0xffffffffu, lA1, 2);
    lB0 += __shfl_xor_sync(0xffffffffu, lB0, 1);
    lB0 += __shfl_xor_sync(0xffffffffu, lB0, 2);
    lB1 += __shfl_xor_sync(0xffffffffu, lB1, 1);
    lB1 += __shfl_xor_sync(0xffffffffu, lB1, 2);

    // ---- store unnormalized partials + (m, l) ----
    const int rA0 = head * LTOK + qw + g;
    const int rA1 = rA0 + 8;
    const int rB0 = rA0 + 16;
    const int rB1 = rA0 + 24;
    float* pA0 = g_pacc + ((size_t)split * NROWS + rA0) * HDIM + 2 * tg;
    float* pA1 = g_pacc + ((size_t)split * NROWS + rA1) * HDIM + 2 * tg;
    float* pB0 = g_pacc + ((size_t)split * NROWS + rB0) * HDIM + 2 * tg;
    float* pB1 = g_pacc + ((size_t)split * NROWS + rB1) * HDIM + 2 * tg;
    #pragma unroll
    for (int nt = 0; nt < 4; nt++) {
        *(float2*)(pA0 + nt * 8) = make_float2(oA[nt][0], oA[nt][1]);
        *(float2*)(pA1 + nt * 8) = make_float2(oA[nt][2], oA[nt][3]);
        *(float2*)(pB0 + nt * 8) = make_float2(oB[nt][0], oB[nt][1]);
        *(float2*)(pB1 + nt * 8) = make_float2(oB[nt][2], oB[nt][3]);
    }
    if (tg == 0) {
        g_pm[split * NROWS + rA0] = mA0;  g_pl[split * NROWS + rA0] = lA0;
        g_pm[split * NROWS + rA1] = mA1;  g_pl[split * NROWS + rA1] = lA1;
        g_pm[split * NROWS + rB0] = mB0;  g_pl[split * NROWS + rB0] = lB0;
        g_pm[split * NROWS + rB1] = mB1;  g_pl[split * NROWS + rB1] = lB1;
    }
}

// ---------------------------------------------------------------------------------
// Merge split-K partials.
// ---------------------------------------------------------------------------------
__global__ void __launch_bounds__(256) merge_kernel()
{
    const int idx = blockIdx.x * 256 + threadIdx.x;
    const int row = idx >> 3, d4 = idx & 7;

    float mv[SPLIT];
    float mstar = -INFINITY;
    #pragma unroll
    for (int s = 0; s < SPLIT; s++) {
        mv[s] = g_pm[s * NROWS + row];
        mstar = fmaxf(mstar, mv[s]);
    }
    float denom = 0.0f;
    float4 o = make_float4(0.f, 0.f, 0.f, 0.f);
    #pragma unroll
    for (int s = 0; s < SPLIT; s++) {
        const float w = __expf(mv[s] - mstar);
        denom = fmaf(w, g_pl[s * NROWS + row], denom);
        const float4 a = *(const float4*)(g_pacc + ((size_t)s * NROWS + row) * HDIM + d4 * 4);
        o.x = fmaf(w, a.x, o.x);
        o.y = fmaf(w, a.y, o.y);
        o.z = fmaf(w, a.z, o.z);
        o.w = fmaf(w, a.w, o.w);
    }
    const float inv = 1.0f / denom;
    o.x *= inv; o.y *= inv; o.z *= inv; o.w *= inv;

    const int head = row >> 11, q = row & (LTOK - 1);
    *(float4*)(g_att + (size_t)q * DMODEL + head * HDIM + d4 * 4) = o;
}

// ---------------------------------------------------------------------------------
// LayerNorm over last dim (256). One block per row.
// ---------------------------------------------------------------------------------
__global__ void __launch_bounds__(256) ln_kernel(
    const float* __restrict__ y, const float* __restrict__ g,
    const float* __restrict__ b, float* __restrict__ out)
{
    __shared__ float red[16];
    const int row = blockIdx.x, t = threadIdx.x;
    const float v = y[row * DMODEL + t];

    float s = v;
    #pragma unroll
    for (int o = 16; o; o >>= 1) s += __shfl_xor_sync(0xffffffffu, s, o);
    if ((t & 31) == 0) red[t >> 5] = s;
    __syncthreads();
    float tot = 0.f;
    #pragma unroll
    for (int w = 0; w < 8; w++) tot += red[w];
    const float mu = tot * (1.0f / 256.0f);

    const float d = v - mu;
    float sq = d * d;
    #pragma unroll
    for (int o = 16; o; o >>= 1) sq += __shfl_xor_sync(0xffffffffu, sq, o);
    if ((t & 31) == 0) red[8 + (t >> 5)] = sq;
    __syncthreads();
    float tot2 = 0.f;
    #pragma unroll
    for (int w = 0; w < 8; w++) tot2 += red[8 + w];
    const float var = tot2 * (1.0f / 256.0f);

    out[row * DMODEL + t] = d * rsqrtf(var + LN_EPS) * g[t] + b[t];
}

// ---------------------------------------------------------------------------------
extern "C" void kernel_launch(void* const* d_in, const int* in_sizes, int n_in,
                              void* d_out, int out_size)
{
    const float* x    = (const float*)d_in[0];
    const float* pts  = (const float*)d_in[1];
    const float* Wq   = (const float*)d_in[2];
    const float* bq   = (const float*)d_in[3];
    const float* Wk   = (const float*)d_in[4];
    const float* bk   = (const float*)d_in[5];
    const float* Wv   = (const float*)d_in[6];
    const float* bv   = (const float*)d_in[7];
    const float* Wo   = (const float*)d_in[8];
    const float* bo   = (const float*)d_in[9];
    const float* beta = (const float*)d_in[10];
    const float* kw1  = (const float*)d_in[11];
    const float* kb1  = (const float*)d_in[12];
    const float* kw2  = (const float*)d_in[13];
    const float* kb2  = (const float*)d_in[14];
    const float* lng  = (const float*)d_in[15];
    const float* lnb  = (const float*)d_in[16];
    float* out = (float*)d_out;

    float *Qb, *Kb, *Vb, *Ab, *Pb;
    cudaGetSymbolAddress((void**)&Qb, g_Q);
    cudaGetSymbolAddress((void**)&Kb, g_K);
    cudaGetSymbolAddress((void**)&Vb, g_V);
    cudaGetSymbolAddress((void**)&Ab, g_att);
    cudaGetSymbolAddress((void**)&Pb, g_proj);

    setup_geo_tables<<<1, 1>>>(kw1, kb1, kw2, kb2);

    gemm_qkv<<<dim3(DMODEL/64, LTOK/64, 3), 128>>>(x, Wq, bq, Wk, bk, Wv, bv, Qb, Kb, Vb);

    geo_bias_kernel<<<LTOK / 4, 256>>>(pts, beta);

    attn_kernel<<<NHEADS * 16 * SPLIT, 128>>>();
    merge_kernel<<<NROWS * 8 / 256, 256>>>();

    gemm_o<<<dim3(DMODEL/64, LTOK/64), 128>>>(Ab, Wo, bo, x, Pb);

    ln_kernel<<<LTOK, 256>>>(Pb, lng, lnb, out);
}